// round 1
// baseline (speedup 1.0000x reference)
#include <cuda_runtime.h>
#include <math.h>

// ---------------- problem constants ----------------
#define B_    32
#define L_    12
#define N_    512
#define D_    128
#define BN_   16384      // B_*N_
#define LBN_  196608     // L_*BN_
#define H_    4
#define HD_   32
#define FK_   256
#define T_    12
#define RES_ELEMS  25165824ULL   // 32*12*512*128
#define FORE_ELEMS 50331648ULL   // 32*12*512*256

// ---------------- device scratch (static, no allocations) ----------------
__device__ float g_Xs    [(size_t)LBN_ * 128];
__device__ float g_GI    [(size_t)LBN_ * 384];
__device__ float g_GH    [(size_t)BN_  * 384];
__device__ float g_rnn   [(size_t)LBN_ * 128];
__device__ float g_rnnpe [(size_t)LBN_ * 128];
__device__ float g_QKV   [(size_t)LBN_ * 384];
__device__ float g_attn  [(size_t)LBN_ * 128];
__device__ float g_Z0    [(size_t)LBN_ * 128];
__device__ float g_back  [(size_t)LBN_ * 128];
__device__ float g_Kc    [(size_t)23 * BN_ * 128];
__device__ float g_Vc    [(size_t)23 * BN_ * 128];
__device__ float g_pred  [(size_t)T_ * BN_ * 128];
__device__ float g_proj  [(size_t)BN_ * 384];
__device__ float g_GIdec [(size_t)BN_ * 384];
__device__ float g_GHdec [(size_t)BN_ * 384];
__device__ float g_g     [(size_t)BN_ * 128];
__device__ float g_hlast [(size_t)BN_ * 128];
__device__ float g_ares  [(size_t)BN_ * 128];
__device__ float g_h0    [(size_t)BN_ * 128];
__device__ float g_pe    [64 * 128];
__device__ float g_Kpe   [24 * 128];
__device__ float g_Vpe   [24 * 128];

// ---------------- SGEMM: C[M,N] = A[M,128] @ W[N,128]^T + bias ----------------
// BM=BN=128, BK=16, 256 threads, 8x8 per thread. M,N multiples of 128. K fixed 128.
// mode 0: plain row-major output. mode 1: forecast permute (T,BN) row -> (B,T,N) row, N=256.
__global__ __launch_bounds__(256) void sgemm_k128(
    const float* __restrict__ A, const float* __restrict__ W,
    const float* __restrict__ bias, float* __restrict__ C,
    int M, int N, int mode)
{
    __shared__ float As[16][128];
    __shared__ float Bs[16][128];

    const int tid = threadIdx.x;
    const int tx = tid & 15;
    const int ty = tid >> 4;
    const int blockM = blockIdx.y * 128;
    const int blockN = blockIdx.x * 128;

    const float* Aptr = A + (size_t)blockM * 128;
    const float* Wptr = W + (size_t)blockN * 128;

    const int ldRow = tid >> 2;         // 0..63
    const int ldK4  = (tid & 3) * 4;    // 0,4,8,12

    float acc[8][8];
    #pragma unroll
    for (int i = 0; i < 8; i++)
        #pragma unroll
        for (int j = 0; j < 8; j++) acc[i][j] = 0.f;

    for (int k0 = 0; k0 < 128; k0 += 16) {
        #pragma unroll
        for (int r = 0; r < 2; r++) {
            int row = ldRow + r * 64;
            float4 va = *(const float4*)(Aptr + (size_t)row * 128 + k0 + ldK4);
            As[ldK4 + 0][row] = va.x; As[ldK4 + 1][row] = va.y;
            As[ldK4 + 2][row] = va.z; As[ldK4 + 3][row] = va.w;
            float4 vb = *(const float4*)(Wptr + (size_t)row * 128 + k0 + ldK4);
            Bs[ldK4 + 0][row] = vb.x; Bs[ldK4 + 1][row] = vb.y;
            Bs[ldK4 + 2][row] = vb.z; Bs[ldK4 + 3][row] = vb.w;
        }
        __syncthreads();
        #pragma unroll
        for (int kk = 0; kk < 16; kk++) {
            float ra[8], rb[8];
            #pragma unroll
            for (int i = 0; i < 8; i++) ra[i] = As[kk][ty * 8 + i];
            #pragma unroll
            for (int j = 0; j < 8; j++) rb[j] = Bs[kk][tx * 8 + j];
            #pragma unroll
            for (int i = 0; i < 8; i++)
                #pragma unroll
                for (int j = 0; j < 8; j++)
                    acc[i][j] += ra[i] * rb[j];
        }
        __syncthreads();
    }

    #pragma unroll
    for (int i = 0; i < 8; i++) {
        int row = blockM + ty * 8 + i;
        if (mode == 0) {
            float* crow = C + (size_t)row * N + blockN + tx * 8;
            #pragma unroll
            for (int j = 0; j < 8; j++)
                crow[j] = acc[i][j] + bias[blockN + tx * 8 + j];
        } else {
            // row = t*16384 + b*512 + n  ->  out row = (b*12+t)*512 + n, N=256
            int t = row >> 14, rem = row & 16383;
            int b = rem >> 9,  n = rem & 511;
            size_t orow = (size_t)(b * 12 + t) * 512 + n;
            float* crow = C + orow * 256 + blockN + tx * 8;
            #pragma unroll
            for (int j = 0; j < 8; j++)
                crow[j] = acc[i][j] + bias[blockN + tx * 8 + j];
        }
    }
}

// ---------------- elementwise / small kernels ----------------
__global__ void pe_init_kernel(float* pe) {
    int idx = blockIdx.x * blockDim.x + threadIdx.x;
    if (idx >= 64 * 128) return;
    int pos = idx >> 7, d = idx & 127;
    int j = d >> 1;
    float div = expf((float)(2 * j) * (-logf(10000.f) / 128.f));
    float ang = (float)pos * div;
    pe[idx] = (d & 1) ? cosf(ang) : sinf(ang);
}

// Kpe[pos][c] = Wk(row c) . pe[pos] ; Vpe likewise (Wk rows 128..255, Wv rows 256..383 of attn_in_w)
__global__ void kvpe_kernel(const float* __restrict__ attn_in_w, const float* __restrict__ pe,
                            float* __restrict__ Kpe, float* __restrict__ Vpe) {
    int idx = blockIdx.x * blockDim.x + threadIdx.x;
    if (idx >= 24 * 256) return;
    int pos = idx >> 8, c = idx & 255;
    const float* wrow = attn_in_w + (size_t)(128 + c) * 128;
    const float* prow = pe + pos * 128;
    float acc = 0.f;
    #pragma unroll 4
    for (int d = 0; d < 128; d++) acc += wrow[d] * prow[d];
    if (c < 128) Kpe[pos * 128 + c] = acc;
    else         Vpe[pos * 128 + (c - 128)] = acc;
}

__global__ void zero_kernel(float* p, int n) {
    int idx = blockIdx.x * blockDim.x + threadIdx.x;
    if (idx < n) p[idx] = 0.f;
}

__global__ void copy_kernel(const float* __restrict__ s, float* __restrict__ d, int n) {
    int idx = blockIdx.x * blockDim.x + threadIdx.x;
    if (idx < n) d[idx] = s[idx];
}

// X(B,L,N,D) -> Xs(L,BN,D)
__global__ void xperm_kernel(const float* __restrict__ X, float* __restrict__ Xs) {
    int idx = blockIdx.x * blockDim.x + threadIdx.x;
    if (idx >= LBN_ * 128) return;
    int d = idx & 127;
    int row = idx >> 7;
    int l = row >> 14, rem = row & 16383;
    int b = rem >> 9,  n = rem & 511;
    Xs[idx] = X[(((size_t)(b * 12 + l) * 512 + n) << 7) + d];
}

// GRU gate fuse: hnew = (1-z)*n + z*h ; optional hnext = hnew + pe_row
__global__ void gru_gates_kernel(const float* __restrict__ gi, const float* __restrict__ gh,
                                 const float* __restrict__ h, float* __restrict__ hnew,
                                 float* __restrict__ hnext, const float* __restrict__ pe_row,
                                 int total) {
    int idx = blockIdx.x * blockDim.x + threadIdx.x;
    if (idx >= total) return;
    int row = idx >> 7, d = idx & 127;
    size_t b3 = (size_t)row * 384;
    float ir = gi[b3 + d],       hr = gh[b3 + d];
    float iz = gi[b3 + 128 + d], hz = gh[b3 + 128 + d];
    float in_ = gi[b3 + 256 + d], hn = gh[b3 + 256 + d];
    float r = 1.f / (1.f + expf(-(ir + hr)));
    float z = 1.f / (1.f + expf(-(iz + hz)));
    float n = tanhf(in_ + r * hn);
    float hv = h[idx];
    float out = (1.f - z) * n + z * hv;
    hnew[idx] = out;
    if (hnext) hnext[idx] = out + pe_row[d];
}

__global__ void add_pe_kernel(const float* __restrict__ src, const float* __restrict__ pe,
                              float* __restrict__ dst) {
    int idx = blockIdx.x * blockDim.x + threadIdx.x;
    if (idx >= LBN_ * 128) return;
    int d = idx & 127;
    int l = (idx >> 7) >> 14;
    dst[idx] = src[idx] + pe[l * 128 + d];
}

// split encoder K,V (with 1x PE baked in) into caches (pos, BN, 128)
__global__ void kvsplit_kernel(const float* __restrict__ QKV, float* __restrict__ Kc,
                               float* __restrict__ Vc) {
    int idx = blockIdx.x * blockDim.x + threadIdx.x;
    if (idx >= LBN_ * 128) return;
    size_t row = (size_t)(idx >> 7);
    int d = idx & 127;
    Kc[idx] = QKV[row * 384 + 128 + d];
    Vc[idx] = QKV[row * 384 + 256 + d];
}

// append new token K,V (no PE) from decode proj into caches at position pos
__global__ void kvappend_kernel(const float* __restrict__ proj, float* __restrict__ Kc,
                                float* __restrict__ Vc, int pos) {
    int idx = blockIdx.x * blockDim.x + threadIdx.x;
    if (idx >= BN_ * 128) return;
    int row = idx >> 7, d = idx & 127;
    size_t dst = ((size_t)pos * BN_ + row) * 128 + d;
    Kc[dst] = proj[(size_t)row * 384 + 128 + d];
    Vc[dst] = proj[(size_t)row * 384 + 256 + d];
}

// ---------------- encoder self-attention (Lq=Lk=12, warp per (bn,head)) ----------------
__global__ void enc_attn_kernel(const float* __restrict__ QKV, float* __restrict__ O) {
    int bn = blockIdx.x;
    int w = threadIdx.x >> 5, lane = threadIdx.x & 31;
    __shared__ float q[4][12][32];
    __shared__ float k[4][12][33];
    __shared__ float v[4][12][33];
    __shared__ float s[4][12][13];

    for (int e = lane; e < 12 * 32; e += 32) {
        int l = e >> 5, d = e & 31;
        size_t base = ((size_t)l * BN_ + bn) * 384 + w * 32 + d;
        q[w][l][d] = QKV[base];
        k[w][l][d] = QKV[base + 128];
        v[w][l][d] = QKV[base + 256];
    }
    __syncwarp();
    const float scale = 0.17677669529663687f; // 1/sqrt(32)
    if (lane < 12) {
        int j = lane;
        #pragma unroll
        for (int i = 0; i < 12; i++) {
            float acc = 0.f;
            #pragma unroll
            for (int d = 0; d < 32; d++) acc += q[w][i][d] * k[w][j][d];
            s[w][i][j] = acc * scale;
        }
    }
    __syncwarp();
    if (lane < 12) {
        int i = lane;
        float mx = -1e30f;
        #pragma unroll
        for (int j = 0; j < 12; j++) mx = fmaxf(mx, s[w][i][j]);
        float sum = 0.f;
        #pragma unroll
        for (int j = 0; j < 12; j++) { float e = expf(s[w][i][j] - mx); s[w][i][j] = e; sum += e; }
        float inv = 1.f / sum;
        #pragma unroll
        for (int j = 0; j < 12; j++) s[w][i][j] *= inv;
    }
    __syncwarp();
    {
        int d = lane;
        #pragma unroll
        for (int i = 0; i < 12; i++) {
            float acc = 0.f;
            #pragma unroll
            for (int j = 0; j < 12; j++) acc += s[w][i][j] * v[w][j][d];
            O[((size_t)i * BN_ + bn) * 128 + w * 32 + d] = acc;
        }
    }
}

// ---------------- decode attention (1 query, len=12+t keys, PE-drift via multipliers) ----------------
__global__ void dec_attn_kernel(const float* __restrict__ proj,
                                const float* __restrict__ Kc, const float* __restrict__ Vc,
                                const float* __restrict__ Kpe, const float* __restrict__ Vpe,
                                float* __restrict__ O, int t) {
    int len = 12 + t;
    int bn = blockIdx.x;
    int w = threadIdx.x >> 5, lane = threadIdx.x & 31;
    __shared__ float qs[4][32];
    __shared__ float Kb[4][23][33];
    __shared__ float Vb[4][23][33];
    __shared__ float aw[4][23];

    qs[w][lane] = proj[(size_t)bn * 384 + w * 32 + lane];
    for (int e = lane; e < len * 32; e += 32) {
        int i = e >> 5, d = e & 31;
        size_t src = ((size_t)i * BN_ + bn) * 128 + w * 32 + d;
        Kb[w][i][d] = Kc[src];
        Vb[w][i][d] = Vc[src];
    }
    __syncwarp();

    float sc = -1e30f;
    int i = lane;
    if (i < len) {
        // encoder tokens cached with 1x PE (need t total); generated token s cached with 0 (need t-s+1)
        float m = (i < 12) ? (float)(t - 1) : (float)(t - i + 12);
        float a = 0.f, ap = 0.f;
        #pragma unroll
        for (int d = 0; d < 32; d++) {
            float qd = qs[w][d];
            a  += Kb[w][i][d] * qd;
            ap += Kpe[i * 128 + w * 32 + d] * qd;
        }
        sc = (a + m * ap) * 0.17677669529663687f;
    }
    float mx = sc;
    #pragma unroll
    for (int o = 16; o > 0; o >>= 1) mx = fmaxf(mx, __shfl_xor_sync(0xffffffffu, mx, o));
    float e = (i < len) ? expf(sc - mx) : 0.f;
    float sum = e;
    #pragma unroll
    for (int o = 16; o > 0; o >>= 1) sum += __shfl_xor_sync(0xffffffffu, sum, o);
    float a = e / sum;
    if (i < len) aw[w][i] = a;
    __syncwarp();

    int d = lane;
    float acc = 0.f;
    for (int j = 0; j < len; j++) {
        float mj = (j < 12) ? (float)(t - 1) : (float)(t - j + 12);
        acc += aw[w][j] * (Vb[w][j][d] + mj * Vpe[j * 128 + w * 32 + d]);
    }
    O[(size_t)bn * 128 + w * 32 + d] = acc;
}

// ---------------- backcast + residual LayerNorm ----------------
__global__ void backln_kernel(const float* __restrict__ X, const float* __restrict__ back,
                              const float* __restrict__ gamma, const float* __restrict__ beta,
                              float* __restrict__ res) {
    int row = blockIdx.x;                 // l*16384 + b*512 + n
    int d = threadIdx.x;                  // 0..127
    int l = row >> 14, rem = row & 16383;
    int b = rem >> 9,  n = rem & 511;
    size_t xbase = ((size_t)(b * 12 + l) * 512 + n) * 128;
    float bk = back[(size_t)row * 128 + d];
    float u = X[xbase + d] - fmaxf(bk, 0.f);
    float s = u, s2 = u * u;
    #pragma unroll
    for (int o = 16; o > 0; o >>= 1) {
        s  += __shfl_xor_sync(0xffffffffu, s, o);
        s2 += __shfl_xor_sync(0xffffffffu, s2, o);
    }
    __shared__ float ss[4], ss2[4];
    int w = d >> 5;
    if ((d & 31) == 0) { ss[w] = s; ss2[w] = s2; }
    __syncthreads();
    s  = ss[0] + ss[1] + ss[2] + ss[3];
    s2 = ss2[0] + ss2[1] + ss2[2] + ss2[3];
    float mu = s * (1.f / 128.f);
    float var = s2 * (1.f / 128.f) - mu * mu;
    res[xbase + d] = (u - mu) * rsqrtf(var + 1e-5f) * gamma[d] + beta[d];
}

// ---------------- host orchestration ----------------
static inline float* symaddr(const void* sym) {
    void* p = nullptr;
    cudaGetSymbolAddress(&p, sym);
    return (float*)p;
}

extern "C" void kernel_launch(void* const* d_in, const int* in_sizes, int n_in,
                              void* d_out, int out_size) {
    const float* X          = (const float*)d_in[0];
    const float* gru_w_ih   = (const float*)d_in[1];
    const float* gru_w_hh   = (const float*)d_in[2];
    const float* gru_b_ih   = (const float*)d_in[3];
    const float* gru_b_hh   = (const float*)d_in[4];
    const float* attn_in_w  = (const float*)d_in[5];
    const float* attn_in_b  = (const float*)d_in[6];
    const float* attn_out_w = (const float*)d_in[7];
    const float* attn_out_b = (const float*)d_in[8];
    const float* backcast_w = (const float*)d_in[9];
    const float* backcast_b = (const float*)d_in[10];
    const float* forecast_w = (const float*)d_in[11];
    const float* forecast_b = (const float*)d_in[12];
    const float* ln_gamma   = (const float*)d_in[13];
    const float* ln_beta    = (const float*)d_in[14];

    float* out  = (float*)d_out;
    float* res  = out;
    float* fore = out + RES_ELEMS;

    float* Xs    = symaddr(g_Xs);
    float* GI    = symaddr(g_GI);
    float* GH    = symaddr(g_GH);
    float* rnn   = symaddr(g_rnn);
    float* rnnpe = symaddr(g_rnnpe);
    float* QKV   = symaddr(g_QKV);
    float* attn  = symaddr(g_attn);
    float* Z0    = symaddr(g_Z0);
    float* back  = symaddr(g_back);
    float* Kc    = symaddr(g_Kc);
    float* Vc    = symaddr(g_Vc);
    float* pred  = symaddr(g_pred);
    float* proj  = symaddr(g_proj);
    float* GIdec = symaddr(g_GIdec);
    float* GHdec = symaddr(g_GHdec);
    float* gbuf  = symaddr(g_g);
    float* hlast = symaddr(g_hlast);
    float* ares  = symaddr(g_ares);
    float* h0    = symaddr(g_h0);
    float* pe    = symaddr(g_pe);
    float* Kpe   = symaddr(g_Kpe);
    float* Vpe   = symaddr(g_Vpe);

    const int TPB = 256;

    // ---- PE table + W*pe projections ----
    pe_init_kernel<<<(64 * 128 + TPB - 1) / TPB, TPB>>>(pe);
    kvpe_kernel<<<(24 * 256 + TPB - 1) / TPB, TPB>>>(attn_in_w, pe, Kpe, Vpe);

    // ---- X -> (L,BN,D) ----
    xperm_kernel<<<LBN_ * 128 / TPB, TPB>>>(X, Xs);

    // ---- GRU encode: gi for all steps in one GEMM, then sequential gh + gates ----
    sgemm_k128<<<dim3(3, LBN_ / 128), 256>>>(Xs, gru_w_ih, gru_b_ih, GI, LBN_, 384, 0);
    zero_kernel<<<BN_ * 128 / TPB, TPB>>>(h0, BN_ * 128);
    const float* hprev = h0;
    for (int l = 0; l < 12; l++) {
        sgemm_k128<<<dim3(3, BN_ / 128), 256>>>(hprev, gru_w_hh, gru_b_hh, GH, BN_, 384, 0);
        gru_gates_kernel<<<BN_ * 128 / TPB, TPB>>>(GI + (size_t)l * BN_ * 384, GH, hprev,
                                                   rnn + (size_t)l * BN_ * 128,
                                                   nullptr, nullptr, BN_ * 128);
        hprev = rnn + (size_t)l * BN_ * 128;
    }

    // ---- encoder MHA ----
    add_pe_kernel<<<LBN_ * 128 / TPB, TPB>>>(rnn, pe, rnnpe);
    sgemm_k128<<<dim3(3, LBN_ / 128), 256>>>(rnnpe, attn_in_w, attn_in_b, QKV, LBN_, 384, 0);
    enc_attn_kernel<<<BN_, 128>>>(QKV, attn);
    sgemm_k128<<<dim3(1, LBN_ / 128), 256>>>(attn, attn_out_w, attn_out_b, Z0, LBN_, 128, 0);
    kvsplit_kernel<<<LBN_ * 128 / TPB, TPB>>>(QKV, Kc, Vc);

    // ---- backcast + residual LN (output part 1) ----
    sgemm_k128<<<dim3(1, LBN_ / 128), 256>>>(Z0, backcast_w, backcast_b, back, LBN_, 128, 0);
    backln_kernel<<<LBN_, 128>>>(X, back, ln_gamma, ln_beta, res);

    // ---- decode loop ----
    copy_kernel<<<BN_ * 128 / TPB, TPB>>>(Z0 + (size_t)11 * BN_ * 128, pred, BN_ * 128);
    const float* hl = rnn + (size_t)11 * BN_ * 128;   // rnn_raw[-1], no PE at t=1
    for (int t = 1; t <= 11; t++) {
        const float* p = pred + (size_t)(t - 1) * BN_ * 128;
        sgemm_k128<<<dim3(3, BN_ / 128), 256>>>(p,  gru_w_ih, gru_b_ih, GIdec, BN_, 384, 0);
        sgemm_k128<<<dim3(3, BN_ / 128), 256>>>(hl, gru_w_hh, gru_b_hh, GHdec, BN_, 384, 0);
        gru_gates_kernel<<<BN_ * 128 / TPB, TPB>>>(GIdec, GHdec, hl, gbuf,
                                                   hlast, pe + (11 + t) * 128, BN_ * 128);
        hl = hlast;
        sgemm_k128<<<dim3(3, BN_ / 128), 256>>>(gbuf, attn_in_w, attn_in_b, proj, BN_, 384, 0);
        kvappend_kernel<<<BN_ * 128 / TPB, TPB>>>(proj, Kc, Vc, 11 + t);
        dec_attn_kernel<<<BN_, 128>>>(proj, Kc, Vc, Kpe, Vpe, ares, t);
        sgemm_k128<<<dim3(1, BN_ / 128), 256>>>(ares, attn_out_w, attn_out_b,
                                                pred + (size_t)t * BN_ * 128, BN_, 128, 0);
    }

    // ---- forecast (output part 2, permuted epilogue) ----
    sgemm_k128<<<dim3(2, LBN_ / 128), 256>>>(pred, forecast_w, forecast_b, fore, LBN_, 256, 1);
}

// round 2
// speedup vs baseline: 1.4690x; 1.4690x over previous
#include <cuda_runtime.h>
#include <math.h>

// ---------------- problem constants ----------------
#define B_    32
#define L_    12
#define N_    512
#define D_    128
#define BN_   16384      // B_*N_
#define LBN_  196608     // L_*BN_
#define H_    4
#define HD_   32
#define FK_   256
#define T_    12
#define RES_ELEMS  25165824ULL   // 32*12*512*128
#define FORE_ELEMS 50331648ULL   // 32*12*512*256

// ---------------- device scratch (static, no allocations) ----------------
__device__ float g_Xs    [(size_t)LBN_ * 128];
__device__ float g_GI    [(size_t)LBN_ * 384];
__device__ float g_GH    [(size_t)BN_  * 384];
__device__ float g_rnn   [(size_t)LBN_ * 128];
__device__ float g_rnnpe [(size_t)LBN_ * 128];
__device__ float g_QKV   [(size_t)LBN_ * 384];
__device__ float g_attn  [(size_t)LBN_ * 128];
__device__ float g_Z0    [(size_t)LBN_ * 128];
__device__ float g_back  [(size_t)LBN_ * 128];
__device__ float g_Kc    [(size_t)23 * BN_ * 128];
__device__ float g_Vc    [(size_t)23 * BN_ * 128];
__device__ float g_pred  [(size_t)T_ * BN_ * 128];
__device__ float g_proj  [(size_t)BN_ * 384];
__device__ float g_GIdec [(size_t)BN_ * 384];
__device__ float g_GHdec [(size_t)BN_ * 384];
__device__ float g_g     [(size_t)BN_ * 128];
__device__ float g_hlast [(size_t)BN_ * 128];
__device__ float g_ares  [(size_t)BN_ * 128];
__device__ float g_h0    [(size_t)BN_ * 128];
__device__ float g_pe    [64 * 128];
__device__ float g_Kpe   [24 * 128];
__device__ float g_Vpe   [24 * 128];

// ---------------- tf32 helpers ----------------
__device__ __forceinline__ unsigned tf32_rna(float x) {
    unsigned u;
    asm("cvt.rna.tf32.f32 %0, %1;" : "=r"(u) : "f"(x));
    return u;
}

__device__ __forceinline__ void mma1688(float c[4], const unsigned a[4], const unsigned b[2]) {
    asm volatile(
        "mma.sync.aligned.m16n8k8.row.col.f32.tf32.tf32.f32 "
        "{%0,%1,%2,%3}, {%4,%5,%6,%7}, {%8,%9}, {%0,%1,%2,%3};\n"
        : "+f"(c[0]), "+f"(c[1]), "+f"(c[2]), "+f"(c[3])
        : "r"(a[0]), "r"(a[1]), "r"(a[2]), "r"(a[3]), "r"(b[0]), "r"(b[1]));
}

// ---------------- tf32 tensor-core GEMM ----------------
// C[M,N] = A[M,128] @ W[N,128]^T + bias. M,N multiples of 128. K fixed 128.
// mode 0: row-major output. mode 1: forecast permute (T,BN) row -> (B,T,N) row (N=256).
// blockIdx.z selects pointer set 0 or 1 (for fused pair launches).
// CTA tile 128x128, 8 warps of 64x32, BK=16 double-buffered.
// smem layout [k][m] with row stride 136 -> fragment LDS bank = (8k + m) % 32, conflict-free.
__global__ __launch_bounds__(256) void gemm_tf32(
    const float* __restrict__ A0, const float* __restrict__ W0,
    const float* __restrict__ bias0, float* __restrict__ C0,
    const float* __restrict__ A1, const float* __restrict__ W1,
    const float* __restrict__ bias1, float* __restrict__ C1,
    int M, int N, int mode)
{
    const float* A    = blockIdx.z ? A1    : A0;
    const float* W    = blockIdx.z ? W1    : W0;
    const float* bias = blockIdx.z ? bias1 : bias0;
    float*       C    = blockIdx.z ? C1    : C0;

    __shared__ unsigned As[2][16][136];
    __shared__ unsigned Ws[2][16][136];

    const int tid  = threadIdx.x;
    const int lane = tid & 31;
    const int warp = tid >> 5;
    const int wm = (warp >> 2) * 64;   // 0,64
    const int wn = (warp & 3) * 32;    // 0,32,64,96

    const int m_ld = tid & 127;        // row within 128-row tile
    const int half = tid >> 7;         // k-half 0/1 (8 k each)

    const int blockM = blockIdx.y * 128;
    const int blockN = blockIdx.x * 128;

    const float* Ag = A + (size_t)(blockM + m_ld) * 128 + 8 * half;
    const float* Wg = W + (size_t)(blockN + m_ld) * 128 + 8 * half;

    float c[4][4][4];
    #pragma unroll
    for (int i = 0; i < 4; i++)
        #pragma unroll
        for (int j = 0; j < 4; j++)
            #pragma unroll
            for (int r = 0; r < 4; r++) c[i][j][r] = 0.f;

    float4 av0, av1, wv0, wv1;

    #define LOADG(IT) do { \
        const float* ap = Ag + (IT) * 16; \
        av0 = *(const float4*)ap; av1 = *(const float4*)(ap + 4); \
        const float* wp = Wg + (IT) * 16; \
        wv0 = *(const float4*)wp; wv1 = *(const float4*)(wp + 4); \
    } while (0)

    #define STS(BUF) do { \
        int kb = 8 * half; \
        As[BUF][kb + 0][m_ld] = tf32_rna(av0.x); As[BUF][kb + 1][m_ld] = tf32_rna(av0.y); \
        As[BUF][kb + 2][m_ld] = tf32_rna(av0.z); As[BUF][kb + 3][m_ld] = tf32_rna(av0.w); \
        As[BUF][kb + 4][m_ld] = tf32_rna(av1.x); As[BUF][kb + 5][m_ld] = tf32_rna(av1.y); \
        As[BUF][kb + 6][m_ld] = tf32_rna(av1.z); As[BUF][kb + 7][m_ld] = tf32_rna(av1.w); \
        Ws[BUF][kb + 0][m_ld] = tf32_rna(wv0.x); Ws[BUF][kb + 1][m_ld] = tf32_rna(wv0.y); \
        Ws[BUF][kb + 2][m_ld] = tf32_rna(wv0.z); Ws[BUF][kb + 3][m_ld] = tf32_rna(wv0.w); \
        Ws[BUF][kb + 4][m_ld] = tf32_rna(wv1.x); Ws[BUF][kb + 5][m_ld] = tf32_rna(wv1.y); \
        Ws[BUF][kb + 6][m_ld] = tf32_rna(wv1.z); Ws[BUF][kb + 7][m_ld] = tf32_rna(wv1.w); \
    } while (0)

    LOADG(0);
    STS(0);
    __syncthreads();

    #pragma unroll
    for (int it = 0; it < 8; it++) {
        if (it < 7) LOADG(it + 1);

        const int buf = it & 1;
        #pragma unroll
        for (int ks = 0; ks < 16; ks += 8) {
            unsigned af[4][4], bf[4][2];
            #pragma unroll
            for (int mt = 0; mt < 4; mt++) {
                int row = wm + mt * 16 + (lane >> 2);
                int kc = ks + (lane & 3);
                af[mt][0] = As[buf][kc][row];
                af[mt][1] = As[buf][kc][row + 8];
                af[mt][2] = As[buf][kc + 4][row];
                af[mt][3] = As[buf][kc + 4][row + 8];
            }
            #pragma unroll
            for (int nt = 0; nt < 4; nt++) {
                int col = wn + nt * 8 + (lane >> 2);
                int kc = ks + (lane & 3);
                bf[nt][0] = Ws[buf][kc][col];
                bf[nt][1] = Ws[buf][kc + 4][col];
            }
            #pragma unroll
            for (int mt = 0; mt < 4; mt++)
                #pragma unroll
                for (int nt = 0; nt < 4; nt++)
                    mma1688(c[mt][nt], af[mt], bf[nt]);
        }

        if (it < 7) STS((it + 1) & 1);
        __syncthreads();
    }
    #undef LOADG
    #undef STS

    // epilogue
    #pragma unroll
    for (int mt = 0; mt < 4; mt++) {
        #pragma unroll
        for (int nt = 0; nt < 4; nt++) {
            int gr0 = blockM + wm + mt * 16 + (lane >> 2);
            int gc  = blockN + wn + nt * 8 + 2 * (lane & 3);
            float bv0 = bias[gc], bv1 = bias[gc + 1];
            if (mode == 0) {
                float* p0 = C + (size_t)gr0 * N + gc;
                float* p1 = C + (size_t)(gr0 + 8) * N + gc;
                p0[0] = c[mt][nt][0] + bv0; p0[1] = c[mt][nt][1] + bv1;
                p1[0] = c[mt][nt][2] + bv0; p1[1] = c[mt][nt][3] + bv1;
            } else {
                int t0 = gr0 >> 14, rem0 = gr0 & 16383;
                int b0r = rem0 >> 9, n0 = rem0 & 511;
                size_t or0 = (size_t)(b0r * 12 + t0) * 512 + n0;
                int gr1 = gr0 + 8;
                int t1 = gr1 >> 14, rem1 = gr1 & 16383;
                int b1r = rem1 >> 9, n1 = rem1 & 511;
                size_t or1 = (size_t)(b1r * 12 + t1) * 512 + n1;
                float* p0 = C + or0 * 256 + gc;
                float* p1 = C + or1 * 256 + gc;
                p0[0] = c[mt][nt][0] + bv0; p0[1] = c[mt][nt][1] + bv1;
                p1[0] = c[mt][nt][2] + bv0; p1[1] = c[mt][nt][3] + bv1;
            }
        }
    }
}

// ---------------- elementwise / small kernels ----------------
__global__ void pe_init_kernel(float* pe) {
    int idx = blockIdx.x * blockDim.x + threadIdx.x;
    if (idx >= 64 * 128) return;
    int pos = idx >> 7, d = idx & 127;
    int j = d >> 1;
    float div = expf((float)(2 * j) * (-logf(10000.f) / 128.f));
    float ang = (float)pos * div;
    pe[idx] = (d & 1) ? cosf(ang) : sinf(ang);
}

__global__ void kvpe_kernel(const float* __restrict__ attn_in_w, const float* __restrict__ pe,
                            float* __restrict__ Kpe, float* __restrict__ Vpe) {
    int idx = blockIdx.x * blockDim.x + threadIdx.x;
    if (idx >= 24 * 256) return;
    int pos = idx >> 8, c = idx & 255;
    const float* wrow = attn_in_w + (size_t)(128 + c) * 128;
    const float* prow = pe + pos * 128;
    float acc = 0.f;
    #pragma unroll 4
    for (int d = 0; d < 128; d++) acc += wrow[d] * prow[d];
    if (c < 128) Kpe[pos * 128 + c] = acc;
    else         Vpe[pos * 128 + (c - 128)] = acc;
}

__global__ void zero_kernel(float* p, int n) {
    int idx = blockIdx.x * blockDim.x + threadIdx.x;
    if (idx < n) p[idx] = 0.f;
}

__global__ void copy_kernel(const float* __restrict__ s, float* __restrict__ d, int n) {
    int idx = blockIdx.x * blockDim.x + threadIdx.x;
    if (idx < n) d[idx] = s[idx];
}

// X(B,L,N,D) -> Xs(L,BN,D)
__global__ void xperm_kernel(const float* __restrict__ X, float* __restrict__ Xs) {
    int idx = blockIdx.x * blockDim.x + threadIdx.x;
    if (idx >= LBN_ * 128) return;
    int d = idx & 127;
    int row = idx >> 7;
    int l = row >> 14, rem = row & 16383;
    int b = rem >> 9,  n = rem & 511;
    Xs[idx] = X[(((size_t)(b * 12 + l) * 512 + n) << 7) + d];
}

// GRU gate fuse: hnew = (1-z)*n + z*h ; optional hnext = hnew + pe_row
__global__ void gru_gates_kernel(const float* __restrict__ gi, const float* __restrict__ gh,
                                 const float* __restrict__ h, float* __restrict__ hnew,
                                 float* __restrict__ hnext, const float* __restrict__ pe_row,
                                 int total) {
    int idx = blockIdx.x * blockDim.x + threadIdx.x;
    if (idx >= total) return;
    int row = idx >> 7, d = idx & 127;
    size_t b3 = (size_t)row * 384;
    float ir = gi[b3 + d],       hr = gh[b3 + d];
    float iz = gi[b3 + 128 + d], hz = gh[b3 + 128 + d];
    float in_ = gi[b3 + 256 + d], hn = gh[b3 + 256 + d];
    float r = 1.f / (1.f + expf(-(ir + hr)));
    float z = 1.f / (1.f + expf(-(iz + hz)));
    float n = tanhf(in_ + r * hn);
    float hv = h[idx];
    float out = (1.f - z) * n + z * hv;
    hnew[idx] = out;
    if (hnext) hnext[idx] = out + pe_row[d];
}

__global__ void add_pe_kernel(const float* __restrict__ src, const float* __restrict__ pe,
                              float* __restrict__ dst) {
    int idx = blockIdx.x * blockDim.x + threadIdx.x;
    if (idx >= LBN_ * 128) return;
    int d = idx & 127;
    int l = (idx >> 7) >> 14;
    dst[idx] = src[idx] + pe[l * 128 + d];
}

// split encoder K,V (with 1x PE baked in) into caches (pos, BN, 128)
__global__ void kvsplit_kernel(const float* __restrict__ QKV, float* __restrict__ Kc,
                               float* __restrict__ Vc) {
    int idx = blockIdx.x * blockDim.x + threadIdx.x;
    if (idx >= LBN_ * 128) return;
    size_t row = (size_t)(idx >> 7);
    int d = idx & 127;
    Kc[idx] = QKV[row * 384 + 128 + d];
    Vc[idx] = QKV[row * 384 + 256 + d];
}

// append new token K,V (no PE) from decode proj into caches at position pos
__global__ void kvappend_kernel(const float* __restrict__ proj, float* __restrict__ Kc,
                                float* __restrict__ Vc, int pos) {
    int idx = blockIdx.x * blockDim.x + threadIdx.x;
    if (idx >= BN_ * 128) return;
    int row = idx >> 7, d = idx & 127;
    size_t dst = ((size_t)pos * BN_ + row) * 128 + d;
    Kc[dst] = proj[(size_t)row * 384 + 128 + d];
    Vc[dst] = proj[(size_t)row * 384 + 256 + d];
}

// ---------------- encoder self-attention (Lq=Lk=12, warp per (bn,head)) ----------------
__global__ void enc_attn_kernel(const float* __restrict__ QKV, float* __restrict__ O) {
    int bn = blockIdx.x;
    int w = threadIdx.x >> 5, lane = threadIdx.x & 31;
    __shared__ float q[4][12][32];
    __shared__ float k[4][12][33];
    __shared__ float v[4][12][33];
    __shared__ float s[4][12][13];

    for (int e = lane; e < 12 * 32; e += 32) {
        int l = e >> 5, d = e & 31;
        size_t base = ((size_t)l * BN_ + bn) * 384 + w * 32 + d;
        q[w][l][d] = QKV[base];
        k[w][l][d] = QKV[base + 128];
        v[w][l][d] = QKV[base + 256];
    }
    __syncwarp();
    const float scale = 0.17677669529663687f; // 1/sqrt(32)
    if (lane < 12) {
        int j = lane;
        #pragma unroll
        for (int i = 0; i < 12; i++) {
            float acc = 0.f;
            #pragma unroll
            for (int d = 0; d < 32; d++) acc += q[w][i][d] * k[w][j][d];
            s[w][i][j] = acc * scale;
        }
    }
    __syncwarp();
    if (lane < 12) {
        int i = lane;
        float mx = -1e30f;
        #pragma unroll
        for (int j = 0; j < 12; j++) mx = fmaxf(mx, s[w][i][j]);
        float sum = 0.f;
        #pragma unroll
        for (int j = 0; j < 12; j++) { float e = expf(s[w][i][j] - mx); s[w][i][j] = e; sum += e; }
        float inv = 1.f / sum;
        #pragma unroll
        for (int j = 0; j < 12; j++) s[w][i][j] *= inv;
    }
    __syncwarp();
    {
        int d = lane;
        #pragma unroll
        for (int i = 0; i < 12; i++) {
            float acc = 0.f;
            #pragma unroll
            for (int j = 0; j < 12; j++) acc += s[w][i][j] * v[w][j][d];
            O[((size_t)i * BN_ + bn) * 128 + w * 32 + d] = acc;
        }
    }
}

// ---------------- decode attention (1 query, len=12+t keys, PE-drift via multipliers) ----------------
__global__ void dec_attn_kernel(const float* __restrict__ proj,
                                const float* __restrict__ Kc, const float* __restrict__ Vc,
                                const float* __restrict__ Kpe, const float* __restrict__ Vpe,
                                float* __restrict__ O, int t) {
    int len = 12 + t;
    int bn = blockIdx.x;
    int w = threadIdx.x >> 5, lane = threadIdx.x & 31;
    __shared__ float qs[4][32];
    __shared__ float Kb[4][23][33];
    __shared__ float Vb[4][23][33];
    __shared__ float aw[4][23];

    qs[w][lane] = proj[(size_t)bn * 384 + w * 32 + lane];
    for (int e = lane; e < len * 32; e += 32) {
        int i = e >> 5, d = e & 31;
        size_t src = ((size_t)i * BN_ + bn) * 128 + w * 32 + d;
        Kb[w][i][d] = Kc[src];
        Vb[w][i][d] = Vc[src];
    }
    __syncwarp();

    float sc = -1e30f;
    int i = lane;
    if (i < len) {
        float m = (i < 12) ? (float)(t - 1) : (float)(t - i + 12);
        float a = 0.f, ap = 0.f;
        #pragma unroll
        for (int d = 0; d < 32; d++) {
            float qd = qs[w][d];
            a  += Kb[w][i][d] * qd;
            ap += Kpe[i * 128 + w * 32 + d] * qd;
        }
        sc = (a + m * ap) * 0.17677669529663687f;
    }
    float mx = sc;
    #pragma unroll
    for (int o = 16; o > 0; o >>= 1) mx = fmaxf(mx, __shfl_xor_sync(0xffffffffu, mx, o));
    float e = (i < len) ? expf(sc - mx) : 0.f;
    float sum = e;
    #pragma unroll
    for (int o = 16; o > 0; o >>= 1) sum += __shfl_xor_sync(0xffffffffu, sum, o);
    float a = e / sum;
    if (i < len) aw[w][i] = a;
    __syncwarp();

    int d = lane;
    float acc = 0.f;
    for (int j = 0; j < len; j++) {
        float mj = (j < 12) ? (float)(t - 1) : (float)(t - j + 12);
        acc += aw[w][j] * (Vb[w][j][d] + mj * Vpe[j * 128 + w * 32 + d]);
    }
    O[(size_t)bn * 128 + w * 32 + d] = acc;
}

// ---------------- backcast + residual LayerNorm ----------------
__global__ void backln_kernel(const float* __restrict__ X, const float* __restrict__ back,
                              const float* __restrict__ gamma, const float* __restrict__ beta,
                              float* __restrict__ res) {
    int row = blockIdx.x;                 // l*16384 + b*512 + n
    int d = threadIdx.x;                  // 0..127
    int l = row >> 14, rem = row & 16383;
    int b = rem >> 9,  n = rem & 511;
    size_t xbase = ((size_t)(b * 12 + l) * 512 + n) * 128;
    float bk = back[(size_t)row * 128 + d];
    float u = X[xbase + d] - fmaxf(bk, 0.f);
    float s = u, s2 = u * u;
    #pragma unroll
    for (int o = 16; o > 0; o >>= 1) {
        s  += __shfl_xor_sync(0xffffffffu, s, o);
        s2 += __shfl_xor_sync(0xffffffffu, s2, o);
    }
    __shared__ float ss[4], ss2[4];
    int w = d >> 5;
    if ((d & 31) == 0) { ss[w] = s; ss2[w] = s2; }
    __syncthreads();
    s  = ss[0] + ss[1] + ss[2] + ss[3];
    s2 = ss2[0] + ss2[1] + ss2[2] + ss2[3];
    float mu = s * (1.f / 128.f);
    float var = s2 * (1.f / 128.f) - mu * mu;
    res[xbase + d] = (u - mu) * rsqrtf(var + 1e-5f) * gamma[d] + beta[d];
}

// ---------------- host orchestration ----------------
static inline float* symaddr(const void* sym) {
    void* p = nullptr;
    cudaGetSymbolAddress(&p, sym);
    return (float*)p;
}

static inline void gemm1(const float* A, const float* W, const float* b, float* C,
                         int M, int N, int mode) {
    gemm_tf32<<<dim3(N / 128, M / 128, 1), 256>>>(A, W, b, C, A, W, b, C, M, N, mode);
}

extern "C" void kernel_launch(void* const* d_in, const int* in_sizes, int n_in,
                              void* d_out, int out_size) {
    const float* X          = (const float*)d_in[0];
    const float* gru_w_ih   = (const float*)d_in[1];
    const float* gru_w_hh   = (const float*)d_in[2];
    const float* gru_b_ih   = (const float*)d_in[3];
    const float* gru_b_hh   = (const float*)d_in[4];
    const float* attn_in_w  = (const float*)d_in[5];
    const float* attn_in_b  = (const float*)d_in[6];
    const float* attn_out_w = (const float*)d_in[7];
    const float* attn_out_b = (const float*)d_in[8];
    const float* backcast_w = (const float*)d_in[9];
    const float* backcast_b = (const float*)d_in[10];
    const float* forecast_w = (const float*)d_in[11];
    const float* forecast_b = (const float*)d_in[12];
    const float* ln_gamma   = (const float*)d_in[13];
    const float* ln_beta    = (const float*)d_in[14];

    float* out  = (float*)d_out;
    float* res  = out;
    float* fore = out + RES_ELEMS;

    float* Xs    = symaddr(g_Xs);
    float* GI    = symaddr(g_GI);
    float* GH    = symaddr(g_GH);
    float* rnn   = symaddr(g_rnn);
    float* rnnpe = symaddr(g_rnnpe);
    float* QKV   = symaddr(g_QKV);
    float* attn  = symaddr(g_attn);
    float* Z0    = symaddr(g_Z0);
    float* back  = symaddr(g_back);
    float* Kc    = symaddr(g_Kc);
    float* Vc    = symaddr(g_Vc);
    float* pred  = symaddr(g_pred);
    float* proj  = symaddr(g_proj);
    float* GIdec = symaddr(g_GIdec);
    float* GHdec = symaddr(g_GHdec);
    float* gbuf  = symaddr(g_g);
    float* hlast = symaddr(g_hlast);
    float* ares  = symaddr(g_ares);
    float* h0    = symaddr(g_h0);
    float* pe    = symaddr(g_pe);
    float* Kpe   = symaddr(g_Kpe);
    float* Vpe   = symaddr(g_Vpe);

    const int TPB = 256;

    // ---- PE table + W*pe projections ----
    pe_init_kernel<<<(64 * 128 + TPB - 1) / TPB, TPB>>>(pe);
    kvpe_kernel<<<(24 * 256 + TPB - 1) / TPB, TPB>>>(attn_in_w, pe, Kpe, Vpe);

    // ---- X -> (L,BN,D) ----
    xperm_kernel<<<LBN_ * 128 / TPB, TPB>>>(X, Xs);

    // ---- GRU encode: gi for all steps in one GEMM, then sequential gh + gates ----
    gemm1(Xs, gru_w_ih, gru_b_ih, GI, LBN_, 384, 0);
    zero_kernel<<<BN_ * 128 / TPB, TPB>>>(h0, BN_ * 128);
    const float* hprev = h0;
    for (int l = 0; l < 12; l++) {
        gemm1(hprev, gru_w_hh, gru_b_hh, GH, BN_, 384, 0);
        gru_gates_kernel<<<BN_ * 128 / TPB, TPB>>>(GI + (size_t)l * BN_ * 384, GH, hprev,
                                                   rnn + (size_t)l * BN_ * 128,
                                                   nullptr, nullptr, BN_ * 128);
        hprev = rnn + (size_t)l * BN_ * 128;
    }

    // ---- encoder MHA ----
    add_pe_kernel<<<LBN_ * 128 / TPB, TPB>>>(rnn, pe, rnnpe);
    gemm1(rnnpe, attn_in_w, attn_in_b, QKV, LBN_, 384, 0);
    enc_attn_kernel<<<BN_, 128>>>(QKV, attn);
    gemm1(attn, attn_out_w, attn_out_b, Z0, LBN_, 128, 0);
    kvsplit_kernel<<<LBN_ * 128 / TPB, TPB>>>(QKV, Kc, Vc);

    // ---- backcast + residual LN (output part 1) ----
    gemm1(Z0, backcast_w, backcast_b, back, LBN_, 128, 0);
    backln_kernel<<<LBN_, 128>>>(X, back, ln_gamma, ln_beta, res);

    // ---- decode loop ----
    copy_kernel<<<BN_ * 128 / TPB, TPB>>>(Z0 + (size_t)11 * BN_ * 128, pred, BN_ * 128);
    const float* hl = rnn + (size_t)11 * BN_ * 128;   // rnn_raw[-1], no PE at t=1
    for (int t = 1; t <= 11; t++) {
        const float* p = pred + (size_t)(t - 1) * BN_ * 128;
        // fused pair: GI = p @ w_ih^T + b_ih ; GH = hl @ w_hh^T + b_hh
        gemm_tf32<<<dim3(3, BN_ / 128, 2), 256>>>(p,  gru_w_ih, gru_b_ih, GIdec,
                                                  hl, gru_w_hh, gru_b_hh, GHdec,
                                                  BN_, 384, 0);
        gru_gates_kernel<<<BN_ * 128 / TPB, TPB>>>(GIdec, GHdec, hl, gbuf,
                                                   hlast, pe + (11 + t) * 128, BN_ * 128);
        hl = hlast;
        gemm1(gbuf, attn_in_w, attn_in_b, proj, BN_, 384, 0);
        kvappend_kernel<<<BN_ * 128 / TPB, TPB>>>(proj, Kc, Vc, 11 + t);
        dec_attn_kernel<<<BN_, 128>>>(proj, Kc, Vc, Kpe, Vpe, ares, t);
        gemm1(ares, attn_out_w, attn_out_b, pred + (size_t)t * BN_ * 128, BN_, 128, 0);
    }

    // ---- forecast (output part 2, permuted epilogue) ----
    gemm1(pred, forecast_w, forecast_b, fore, LBN_, 256, 1);
}

// round 3
// speedup vs baseline: 1.8016x; 1.2264x over previous
#include <cuda_runtime.h>
#include <math.h>
#include <stdint.h>

// ---------------- problem constants ----------------
#define B_    32
#define L_    12
#define N_    512
#define D_    128
#define BN_   16384      // B_*N_
#define LBN_  196608     // L_*BN_
#define FK_   256
#define T_    12
#define RES_ELEMS  25165824ULL   // 32*12*512*128
#define FORE_ELEMS 50331648ULL

// ---------------- device scratch (static, no allocations) ----------------
__device__ float g_Xs    [(size_t)LBN_ * 128];
__device__ float g_GI    [(size_t)LBN_ * 384];
__device__ float g_GH    [(size_t)BN_  * 384];
__device__ float g_rnn   [(size_t)LBN_ * 128];
__device__ float g_rnnpe [(size_t)LBN_ * 128];
__device__ float g_QKV   [(size_t)LBN_ * 384];
__device__ float g_attn  [(size_t)LBN_ * 128];
__device__ float g_Z0    [(size_t)LBN_ * 128];
__device__ float g_back  [(size_t)LBN_ * 128];
__device__ float g_Kc    [(size_t)23 * BN_ * 128];
__device__ float g_Vc    [(size_t)23 * BN_ * 128];
__device__ float g_pred  [(size_t)T_ * BN_ * 128];
__device__ float g_aresT [(size_t)11 * BN_ * 128];
__device__ float g_Qbuf  [(size_t)BN_ * 128];
__device__ float g_GIdec [(size_t)BN_ * 384];
__device__ float g_GHdec [(size_t)BN_ * 384];
__device__ float g_g     [(size_t)BN_ * 128];
__device__ float g_hlast [(size_t)BN_ * 128];
__device__ float g_h0    [(size_t)BN_ * 128];
__device__ float g_pe    [64 * 128];
__device__ float g_Kpe   [24 * 128];
__device__ float g_Vpe   [24 * 128];
// pre-rounded (tf32) weights
__device__ float g_wih_r  [49152];
__device__ float g_whh_r  [49152];
__device__ float g_inw_r  [49152];
__device__ float g_outw_r [16384];
__device__ float g_backw_r[16384];
__device__ float g_forew_r[32768];
__device__ float g_Wf     [49152];
__device__ float g_bf     [384];

// ---------------- tf32 helpers ----------------
__device__ __forceinline__ float rnd_tf32(float x) {
    unsigned u;
    asm("cvt.rna.tf32.f32 %0, %1;" : "=r"(u) : "f"(x));
    return __uint_as_float(u);
}

__device__ __forceinline__ void mma1688(float c[4], const unsigned a[4], const unsigned b[2]) {
    asm volatile(
        "mma.sync.aligned.m16n8k8.row.col.f32.tf32.tf32.f32 "
        "{%0,%1,%2,%3}, {%4,%5,%6,%7}, {%8,%9}, {%0,%1,%2,%3};\n"
        : "+f"(c[0]), "+f"(c[1]), "+f"(c[2]), "+f"(c[3])
        : "r"(a[0]), "r"(a[1]), "r"(a[2]), "r"(a[3]), "r"(b[0]), "r"(b[1]));
}

// ---------------- tf32 GEMM v3: cp.async 3-stage, no cvt in mainloop ----------------
// C[M,N] = A[M,128] @ W[N,128]^T + bias ; A and W must be pre-rounded to tf32.
// modes: 0 plain, 1 plain+tf32-rounded output, 2 forecast permute (N=256),
//        3 QKV: write C full, scatter cols[128,384) into Kc/Vc at row index (N=384),
//        4 proj: cols[0,128)->C (stride 128), cols[128,384) scatter to Kc/Vc at pos (N=384)
// blockIdx.z selects pointer set (fused pair launches).
#define GSMEM_WORDS (2 * 3 * 2560)
__global__ __launch_bounds__(256, 2) void gemm3(
    const float* __restrict__ A0, const float* __restrict__ W0,
    const float* __restrict__ bias0, float* __restrict__ C0,
    const float* __restrict__ A1, const float* __restrict__ W1,
    const float* __restrict__ bias1, float* __restrict__ C1,
    int M, int N, int mode, int pos,
    float* __restrict__ Kc, float* __restrict__ Vc)
{
    extern __shared__ float sm[];
    const float* A    = blockIdx.z ? A1    : A0;
    const float* W    = blockIdx.z ? W1    : W0;
    const float* bias = blockIdx.z ? bias1 : bias0;
    float*       C    = blockIdx.z ? C1    : C0;

    const int tid = threadIdx.x, lane = tid & 31, warp = tid >> 5;
    const int wm = (warp >> 2) * 64;
    const int wn = (warp & 3) * 32;
    const int blockM = blockIdx.y * 128;
    const int blockN = blockIdx.x * 128;

    const int arow = tid >> 1;
    const int koff = (tid & 1) * 8;
    const float* Ag = A + (size_t)(blockM + arow) * 128 + koff;
    const float* Wg = W + (size_t)(blockN + arow) * 128 + koff;
    uint32_t smb = (uint32_t)__cvta_generic_to_shared(sm);
    uint32_t a_s0 = smb + (uint32_t)(arow * 20 + koff) * 4;
    uint32_t w_s0 = smb + (uint32_t)(7680 + arow * 20 + koff) * 4;

    #define CP16(dst, src) asm volatile("cp.async.cg.shared.global [%0], [%1], 16;" :: "r"(dst), "l"(src))
    #define LOADSTAGE(S, KB) do { \
        uint32_t as_ = a_s0 + (S) * 2560u * 4u; const float* ag_ = Ag + (KB); \
        CP16(as_, ag_); CP16(as_ + 16, ag_ + 4); \
        uint32_t ws_ = w_s0 + (S) * 2560u * 4u; const float* wg_ = Wg + (KB); \
        CP16(ws_, wg_); CP16(ws_ + 16, wg_ + 4); \
    } while (0)

    float c[4][4][4];
    #pragma unroll
    for (int i = 0; i < 4; i++)
        #pragma unroll
        for (int j = 0; j < 4; j++)
            #pragma unroll
            for (int r = 0; r < 4; r++) c[i][j][r] = 0.f;

    LOADSTAGE(0, 0);
    asm volatile("cp.async.commit_group;");
    LOADSTAGE(1, 16);
    asm volatile("cp.async.commit_group;");

    #pragma unroll
    for (int it = 0; it < 8; ++it) {
        asm volatile("cp.async.wait_group 1;");
        __syncthreads();
        if (it + 2 < 8) LOADSTAGE((it + 2) % 3, (it + 2) * 16);
        asm volatile("cp.async.commit_group;");

        const float* Ab = sm + (it % 3) * 2560;
        const float* Wb = sm + 7680 + (it % 3) * 2560;
        #pragma unroll
        for (int ks = 0; ks < 16; ks += 8) {
            unsigned af[4][4], bf_[4][2];
            const int kc = ks + (lane & 3);
            #pragma unroll
            for (int mt = 0; mt < 4; mt++) {
                int row = wm + mt * 16 + (lane >> 2);
                af[mt][0] = __float_as_uint(Ab[row * 20 + kc]);
                af[mt][1] = __float_as_uint(Ab[(row + 8) * 20 + kc]);
                af[mt][2] = __float_as_uint(Ab[row * 20 + kc + 4]);
                af[mt][3] = __float_as_uint(Ab[(row + 8) * 20 + kc + 4]);
            }
            #pragma unroll
            for (int nt = 0; nt < 4; nt++) {
                int col = wn + nt * 8 + (lane >> 2);
                bf_[nt][0] = __float_as_uint(Wb[col * 20 + kc]);
                bf_[nt][1] = __float_as_uint(Wb[col * 20 + kc + 4]);
            }
            #pragma unroll
            for (int mt = 0; mt < 4; mt++)
                #pragma unroll
                for (int nt = 0; nt < 4; nt++)
                    mma1688(c[mt][nt], af[mt], bf_[nt]);
        }
    }
    #undef LOADSTAGE
    #undef CP16

    // ---- epilogue ----
    #pragma unroll
    for (int mt = 0; mt < 4; mt++) {
        #pragma unroll
        for (int nt = 0; nt < 4; nt++) {
            int gr = blockM + wm + mt * 16 + (lane >> 2);
            int gc = blockN + wn + nt * 8 + 2 * (lane & 3);
            float bv0 = bias[gc], bv1 = bias[gc + 1];
            float v00 = c[mt][nt][0] + bv0, v01 = c[mt][nt][1] + bv1;
            float v10 = c[mt][nt][2] + bv0, v11 = c[mt][nt][3] + bv1;
            int gr1 = gr + 8;
            if (mode == 0) {
                float* p0 = C + (size_t)gr * N + gc;
                float* p1 = C + (size_t)gr1 * N + gc;
                p0[0] = v00; p0[1] = v01; p1[0] = v10; p1[1] = v11;
            } else if (mode == 1) {
                float* p0 = C + (size_t)gr * N + gc;
                float* p1 = C + (size_t)gr1 * N + gc;
                p0[0] = rnd_tf32(v00); p0[1] = rnd_tf32(v01);
                p1[0] = rnd_tf32(v10); p1[1] = rnd_tf32(v11);
            } else if (mode == 2) {
                int t0 = gr >> 14, rem0 = gr & 16383;
                size_t or0 = (size_t)((rem0 >> 9) * 12 + t0) * 512 + (rem0 & 511);
                int t1 = gr1 >> 14, rem1 = gr1 & 16383;
                size_t or1 = (size_t)((rem1 >> 9) * 12 + t1) * 512 + (rem1 & 511);
                float* p0 = C + or0 * 256 + gc;
                float* p1 = C + or1 * 256 + gc;
                p0[0] = v00; p0[1] = v01; p1[0] = v10; p1[1] = v11;
            } else if (mode == 3) {
                float* p0 = C + (size_t)gr * N + gc;
                float* p1 = C + (size_t)gr1 * N + gc;
                p0[0] = v00; p0[1] = v01; p1[0] = v10; p1[1] = v11;
                if (gc >= 128 && gc < 256) {
                    Kc[(size_t)gr * 128 + gc - 128]  = v00;
                    Kc[(size_t)gr * 128 + gc - 127]  = v01;
                    Kc[(size_t)gr1 * 128 + gc - 128] = v10;
                    Kc[(size_t)gr1 * 128 + gc - 127] = v11;
                } else if (gc >= 256) {
                    Vc[(size_t)gr * 128 + gc - 256]  = v00;
                    Vc[(size_t)gr * 128 + gc - 255]  = v01;
                    Vc[(size_t)gr1 * 128 + gc - 256] = v10;
                    Vc[(size_t)gr1 * 128 + gc - 255] = v11;
                }
            } else { // mode 4
                if (gc < 128) {
                    float* p0 = C + (size_t)gr * 128 + gc;
                    float* p1 = C + (size_t)gr1 * 128 + gc;
                    p0[0] = v00; p0[1] = v01; p1[0] = v10; p1[1] = v11;
                } else if (gc < 256) {
                    size_t b0 = ((size_t)pos * BN_ + gr) * 128 + gc - 128;
                    size_t b1 = ((size_t)pos * BN_ + gr1) * 128 + gc - 128;
                    Kc[b0] = v00; Kc[b0 + 1] = v01; Kc[b1] = v10; Kc[b1 + 1] = v11;
                } else {
                    size_t b0 = ((size_t)pos * BN_ + gr) * 128 + gc - 256;
                    size_t b1 = ((size_t)pos * BN_ + gr1) * 128 + gc - 256;
                    Vc[b0] = v00; Vc[b0 + 1] = v01; Vc[b1] = v10; Vc[b1 + 1] = v11;
                }
            }
        }
    }
}

// ---------------- weight prep ----------------
__global__ void roundw_kernel(const float* __restrict__ w_ih, const float* __restrict__ w_hh,
                              const float* __restrict__ in_w, const float* __restrict__ out_w,
                              const float* __restrict__ back_w, const float* __restrict__ fore_w,
                              float* wih_r, float* whh_r, float* inw_r, float* outw_r,
                              float* backw_r, float* forew_r) {
    int i = blockIdx.x * blockDim.x + threadIdx.x;
    if (i < 49152)       wih_r[i]            = rnd_tf32(w_ih[i]);
    else if (i < 98304)  whh_r[i - 49152]    = rnd_tf32(w_hh[i - 49152]);
    else if (i < 147456) inw_r[i - 98304]    = rnd_tf32(in_w[i - 98304]);
    else if (i < 163840) outw_r[i - 147456]  = rnd_tf32(out_w[i - 147456]);
    else if (i < 180224) backw_r[i - 163840] = rnd_tf32(back_w[i - 163840]);
    else if (i < 212992) forew_r[i - 180224] = rnd_tf32(fore_w[i - 180224]);
}

// Wf = w_ih @ attn_out_w (384x128), bf = w_ih @ b_out + b_ih
__global__ void wf_build_kernel(const float* __restrict__ w_ih, const float* __restrict__ out_w,
                                const float* __restrict__ b_out, const float* __restrict__ b_ih,
                                float* __restrict__ Wf, float* __restrict__ bf) {
    int idx = blockIdx.x * blockDim.x + threadIdx.x;
    if (idx >= 384 * 128) return;
    int r = idx >> 7, k = idx & 127;
    float acc = 0.f;
    #pragma unroll 4
    for (int j = 0; j < 128; j++) acc += w_ih[r * 128 + j] * out_w[j * 128 + k];
    Wf[idx] = rnd_tf32(acc);
    if (k == 0) {
        float b = 0.f;
        for (int j = 0; j < 128; j++) b += w_ih[r * 128 + j] * b_out[j];
        bf[r] = b + b_ih[r];
    }
}

// ---------------- elementwise / small kernels ----------------
__global__ void pe_init_kernel(float* pe) {
    int idx = blockIdx.x * blockDim.x + threadIdx.x;
    if (idx >= 64 * 128) return;
    int pos = idx >> 7, d = idx & 127;
    int j = d >> 1;
    float div = expf((float)(2 * j) * (-logf(10000.f) / 128.f));
    float ang = (float)pos * div;
    pe[idx] = (d & 1) ? cosf(ang) : sinf(ang);
}

__global__ void kvpe_kernel(const float* __restrict__ attn_in_w, const float* __restrict__ pe,
                            float* __restrict__ Kpe, float* __restrict__ Vpe) {
    int idx = blockIdx.x * blockDim.x + threadIdx.x;
    if (idx >= 24 * 256) return;
    int pos = idx >> 8, c = idx & 255;
    const float* wrow = attn_in_w + (size_t)(128 + c) * 128;
    const float* prow = pe + pos * 128;
    float acc = 0.f;
    #pragma unroll 4
    for (int d = 0; d < 128; d++) acc += wrow[d] * prow[d];
    if (c < 128) Kpe[pos * 128 + c] = acc;
    else         Vpe[pos * 128 + (c - 128)] = acc;
}

__global__ void zero_kernel(float* p, int n) {
    int idx = blockIdx.x * blockDim.x + threadIdx.x;
    if (idx < n) p[idx] = 0.f;
}

__global__ void copy_kernel(const float* __restrict__ s, float* __restrict__ d, int n) {
    int idx = blockIdx.x * blockDim.x + threadIdx.x;
    if (idx < n) d[idx] = s[idx];
}

// X(B,L,N,D) -> Xs(L,BN,D), rounded to tf32 (GEMM-A input)
__global__ void xperm_kernel(const float* __restrict__ X, float* __restrict__ Xs) {
    int idx = blockIdx.x * blockDim.x + threadIdx.x;
    if (idx >= LBN_ * 128) return;
    int d = idx & 127;
    int row = idx >> 7;
    int l = row >> 14, rem = row & 16383;
    int b = rem >> 9,  n = rem & 511;
    Xs[idx] = rnd_tf32(X[(((size_t)(b * 12 + l) * 512 + n) << 7) + d]);
}

// GRU gate fuse; hnew / hnext rounded (they feed GEMMs)
__global__ void gru_gates_kernel(const float* __restrict__ gi, const float* __restrict__ gh,
                                 const float* __restrict__ h, float* __restrict__ hnew,
                                 float* __restrict__ hnext, const float* __restrict__ pe_row,
                                 int total) {
    int idx = blockIdx.x * blockDim.x + threadIdx.x;
    if (idx >= total) return;
    int row = idx >> 7, d = idx & 127;
    size_t b3 = (size_t)row * 384;
    float ir = gi[b3 + d],        hr = gh[b3 + d];
    float iz = gi[b3 + 128 + d],  hz = gh[b3 + 128 + d];
    float in_ = gi[b3 + 256 + d], hn = gh[b3 + 256 + d];
    float r = 1.f / (1.f + expf(-(ir + hr)));
    float z = 1.f / (1.f + expf(-(iz + hz)));
    float n = tanhf(in_ + r * hn);
    float hv = h[idx];
    float out = (1.f - z) * n + z * hv;
    hnew[idx] = rnd_tf32(out);
    if (hnext) hnext[idx] = rnd_tf32(out + pe_row[d]);
}

__global__ void add_pe_kernel(const float* __restrict__ src, const float* __restrict__ pe,
                              float* __restrict__ dst) {
    int idx = blockIdx.x * blockDim.x + threadIdx.x;
    if (idx >= LBN_ * 128) return;
    int d = idx & 127;
    int l = (idx >> 7) >> 14;
    dst[idx] = rnd_tf32(src[idx] + pe[l * 128 + d]);
}

// ---------------- encoder self-attention (warp per (bn,head)), output rounded ----------------
__global__ void enc_attn_kernel(const float* __restrict__ QKV, float* __restrict__ O) {
    int bn = blockIdx.x;
    int w = threadIdx.x >> 5, lane = threadIdx.x & 31;
    __shared__ float q[4][12][32];
    __shared__ float k[4][12][33];
    __shared__ float v[4][12][33];
    __shared__ float s[4][12][13];

    for (int e = lane; e < 12 * 32; e += 32) {
        int l = e >> 5, d = e & 31;
        size_t base = ((size_t)l * BN_ + bn) * 384 + w * 32 + d;
        q[w][l][d] = QKV[base];
        k[w][l][d] = QKV[base + 128];
        v[w][l][d] = QKV[base + 256];
    }
    __syncwarp();
    const float scale = 0.17677669529663687f;
    if (lane < 12) {
        int j = lane;
        #pragma unroll
        for (int i = 0; i < 12; i++) {
            float acc = 0.f;
            #pragma unroll
            for (int d = 0; d < 32; d++) acc += q[w][i][d] * k[w][j][d];
            s[w][i][j] = acc * scale;
        }
    }
    __syncwarp();
    if (lane < 12) {
        int i = lane;
        float mx = -1e30f;
        #pragma unroll
        for (int j = 0; j < 12; j++) mx = fmaxf(mx, s[w][i][j]);
        float sum = 0.f;
        #pragma unroll
        for (int j = 0; j < 12; j++) { float e = expf(s[w][i][j] - mx); s[w][i][j] = e; sum += e; }
        float inv = 1.f / sum;
        #pragma unroll
        for (int j = 0; j < 12; j++) s[w][i][j] *= inv;
    }
    __syncwarp();
    {
        int d = lane;
        #pragma unroll
        for (int i = 0; i < 12; i++) {
            float acc = 0.f;
            #pragma unroll
            for (int j = 0; j < 12; j++) acc += s[w][i][j] * v[w][j][d];
            O[((size_t)i * BN_ + bn) * 128 + w * 32 + d] = rnd_tf32(acc);
        }
    }
}

// ---------------- decode attention (q from Qbuf; PE-drift multipliers), output rounded ----------------
__global__ void dec_attn_kernel(const float* __restrict__ Qbuf,
                                const float* __restrict__ Kc, const float* __restrict__ Vc,
                                const float* __restrict__ Kpe, const float* __restrict__ Vpe,
                                float* __restrict__ O, int t) {
    int len = 12 + t;
    int bn = blockIdx.x;
    int w = threadIdx.x >> 5, lane = threadIdx.x & 31;
    __shared__ float qs[4][32];
    __shared__ float Kb[4][23][33];
    __shared__ float Vb[4][23][33];
    __shared__ float aw[4][23];

    qs[w][lane] = Qbuf[(size_t)bn * 128 + w * 32 + lane];
    for (int e = lane; e < len * 32; e += 32) {
        int i = e >> 5, d = e & 31;
        size_t src = ((size_t)i * BN_ + bn) * 128 + w * 32 + d;
        Kb[w][i][d] = Kc[src];
        Vb[w][i][d] = Vc[src];
    }
    __syncwarp();

    float sc = -1e30f;
    int i = lane;
    if (i < len) {
        float m = (i < 12) ? (float)(t - 1) : (float)(t - i + 12);
        float a = 0.f, ap = 0.f;
        #pragma unroll
        for (int d = 0; d < 32; d++) {
            float qd = qs[w][d];
            a  += Kb[w][i][d] * qd;
            ap += Kpe[i * 128 + w * 32 + d] * qd;
        }
        sc = (a + m * ap) * 0.17677669529663687f;
    }
    float mx = sc;
    #pragma unroll
    for (int o = 16; o > 0; o >>= 1) mx = fmaxf(mx, __shfl_xor_sync(0xffffffffu, mx, o));
    float e = (i < len) ? expf(sc - mx) : 0.f;
    float sum = e;
    #pragma unroll
    for (int o = 16; o > 0; o >>= 1) sum += __shfl_xor_sync(0xffffffffu, sum, o);
    float a = e / sum;
    if (i < len) aw[w][i] = a;
    __syncwarp();

    int d = lane;
    float acc = 0.f;
    for (int j = 0; j < len; j++) {
        float mj = (j < 12) ? (float)(t - 1) : (float)(t - j + 12);
        acc += aw[w][j] * (Vb[w][j][d] + mj * Vpe[j * 128 + w * 32 + d]);
    }
    O[(size_t)bn * 128 + w * 32 + d] = rnd_tf32(acc);
}

// ---------------- backcast + residual LayerNorm ----------------
__global__ void backln_kernel(const float* __restrict__ X, const float* __restrict__ back,
                              const float* __restrict__ gamma, const float* __restrict__ beta,
                              float* __restrict__ res) {
    int row = blockIdx.x;
    int d = threadIdx.x;
    int l = row >> 14, rem = row & 16383;
    int b = rem >> 9,  n = rem & 511;
    size_t xbase = ((size_t)(b * 12 + l) * 512 + n) * 128;
    float bk = back[(size_t)row * 128 + d];
    float u = X[xbase + d] - fmaxf(bk, 0.f);
    float s = u, s2 = u * u;
    #pragma unroll
    for (int o = 16; o > 0; o >>= 1) {
        s  += __shfl_xor_sync(0xffffffffu, s, o);
        s2 += __shfl_xor_sync(0xffffffffu, s2, o);
    }
    __shared__ float ss[4], ss2[4];
    int w = d >> 5;
    if ((d & 31) == 0) { ss[w] = s; ss2[w] = s2; }
    __syncthreads();
    s  = ss[0] + ss[1] + ss[2] + ss[3];
    s2 = ss2[0] + ss2[1] + ss2[2] + ss2[3];
    float mu = s * (1.f / 128.f);
    float var = s2 * (1.f / 128.f) - mu * mu;
    res[xbase + d] = (u - mu) * rsqrtf(var + 1e-5f) * gamma[d] + beta[d];
}

// ---------------- host orchestration ----------------
static inline float* symaddr(const void* sym) {
    void* p = nullptr;
    cudaGetSymbolAddress(&p, sym);
    return (float*)p;
}

#define GSMEM_BYTES (GSMEM_WORDS * 4)

static inline void gemm1(const float* A, const float* W, const float* b, float* C,
                         int M, int N, int mode, int pos, float* Kc, float* Vc) {
    gemm3<<<dim3(N / 128, M / 128, 1), 256, GSMEM_BYTES>>>(A, W, b, C, A, W, b, C,
                                                           M, N, mode, pos, Kc, Vc);
}

extern "C" void kernel_launch(void* const* d_in, const int* in_sizes, int n_in,
                              void* d_out, int out_size) {
    const float* X          = (const float*)d_in[0];
    const float* gru_w_ih   = (const float*)d_in[1];
    const float* gru_w_hh   = (const float*)d_in[2];
    const float* gru_b_ih   = (const float*)d_in[3];
    const float* gru_b_hh   = (const float*)d_in[4];
    const float* attn_in_w  = (const float*)d_in[5];
    const float* attn_in_b  = (const float*)d_in[6];
    const float* attn_out_w = (const float*)d_in[7];
    const float* attn_out_b = (const float*)d_in[8];
    const float* backcast_w = (const float*)d_in[9];
    const float* backcast_b = (const float*)d_in[10];
    const float* forecast_w = (const float*)d_in[11];
    const float* forecast_b = (const float*)d_in[12];
    const float* ln_gamma   = (const float*)d_in[13];
    const float* ln_beta    = (const float*)d_in[14];

    float* out  = (float*)d_out;
    float* res  = out;
    float* fore = out + RES_ELEMS;

    float* Xs    = symaddr(g_Xs);
    float* GI    = symaddr(g_GI);
    float* GH    = symaddr(g_GH);
    float* rnn   = symaddr(g_rnn);
    float* rnnpe = symaddr(g_rnnpe);
    float* QKV   = symaddr(g_QKV);
    float* attn  = symaddr(g_attn);
    float* Z0    = symaddr(g_Z0);
    float* back  = symaddr(g_back);
    float* Kc    = symaddr(g_Kc);
    float* Vc    = symaddr(g_Vc);
    float* pred  = symaddr(g_pred);
    float* aresT = symaddr(g_aresT);
    float* Qbuf  = symaddr(g_Qbuf);
    float* GIdec = symaddr(g_GIdec);
    float* GHdec = symaddr(g_GHdec);
    float* gbuf  = symaddr(g_g);
    float* hlast = symaddr(g_hlast);
    float* h0    = symaddr(g_h0);
    float* pe    = symaddr(g_pe);
    float* Kpe   = symaddr(g_Kpe);
    float* Vpe   = symaddr(g_Vpe);
    float* wih_r  = symaddr(g_wih_r);
    float* whh_r  = symaddr(g_whh_r);
    float* inw_r  = symaddr(g_inw_r);
    float* outw_r = symaddr(g_outw_r);
    float* backw_r= symaddr(g_backw_r);
    float* forew_r= symaddr(g_forew_r);
    float* Wf     = symaddr(g_Wf);
    float* bf     = symaddr(g_bf);

    cudaFuncSetAttribute(gemm3, cudaFuncAttributeMaxDynamicSharedMemorySize, GSMEM_BYTES);

    const int TPB = 256;

    // ---- prep: PE table, K/V PE projections, rounded weights, fused Wf/bf ----
    pe_init_kernel<<<(64 * 128 + TPB - 1) / TPB, TPB>>>(pe);
    kvpe_kernel<<<(24 * 256 + TPB - 1) / TPB, TPB>>>(attn_in_w, pe, Kpe, Vpe);
    roundw_kernel<<<(212992 + TPB - 1) / TPB, TPB>>>(gru_w_ih, gru_w_hh, attn_in_w,
                                                     attn_out_w, backcast_w, forecast_w,
                                                     wih_r, whh_r, inw_r, outw_r, backw_r, forew_r);
    wf_build_kernel<<<(49152 + TPB - 1) / TPB, TPB>>>(gru_w_ih, attn_out_w, attn_out_b,
                                                      gru_b_ih, Wf, bf);

    // ---- X -> (L,BN,D) rounded ----
    xperm_kernel<<<LBN_ * 128 / TPB, TPB>>>(X, Xs);

    // ---- GRU encode ----
    gemm1(Xs, wih_r, gru_b_ih, GI, LBN_, 384, 0, 0, nullptr, nullptr);
    zero_kernel<<<BN_ * 128 / TPB, TPB>>>(h0, BN_ * 128);
    const float* hprev = h0;
    for (int l = 0; l < 12; l++) {
        gemm1(hprev, whh_r, gru_b_hh, GH, BN_, 384, 0, 0, nullptr, nullptr);
        gru_gates_kernel<<<BN_ * 128 / TPB, TPB>>>(GI + (size_t)l * BN_ * 384, GH, hprev,
                                                   rnn + (size_t)l * BN_ * 128,
                                                   nullptr, nullptr, BN_ * 128);
        hprev = rnn + (size_t)l * BN_ * 128;
    }

    // ---- encoder MHA (QKV gemm also scatters K/V into caches) ----
    add_pe_kernel<<<LBN_ * 128 / TPB, TPB>>>(rnn, pe, rnnpe);
    gemm1(rnnpe, inw_r, attn_in_b, QKV, LBN_, 384, 3, 0, Kc, Vc);
    enc_attn_kernel<<<BN_, 128>>>(QKV, attn);
    gemm1(attn, outw_r, attn_out_b, Z0, LBN_, 128, 1, 0, nullptr, nullptr);  // rounded

    // ---- backcast + residual LN ----
    gemm1(Z0, backw_r, backcast_b, back, LBN_, 128, 0, 0, nullptr, nullptr);
    backln_kernel<<<LBN_, 128>>>(X, back, ln_gamma, ln_beta, res);

    // ---- decode loop (out-projection fused into next GI via Wf) ----
    copy_kernel<<<BN_ * 128 / TPB, TPB>>>(Z0 + (size_t)11 * BN_ * 128, pred, BN_ * 128);
    const float* hl = rnn + (size_t)11 * BN_ * 128;
    for (int t = 1; t <= 11; t++) {
        const float* prevA = (t == 1) ? attn + (size_t)11 * BN_ * 128
                                      : aresT + (size_t)(t - 2) * BN_ * 128;
        // fused pair: GIdec = prevA @ Wf^T + bf ; GHdec = hl @ w_hh^T + b_hh
        gemm3<<<dim3(3, BN_ / 128, 2), 256, GSMEM_BYTES>>>(
            prevA, Wf, bf, GIdec, hl, whh_r, gru_b_hh, GHdec,
            BN_, 384, 0, 0, nullptr, nullptr);
        gru_gates_kernel<<<BN_ * 128 / TPB, TPB>>>(GIdec, GHdec, hl, gbuf,
                                                   hlast, pe + (11 + t) * 128, BN_ * 128);
        hl = hlast;
        // proj gemm: Q -> Qbuf, K/V scattered straight into caches at pos 11+t
        gemm1(gbuf, inw_r, attn_in_b, Qbuf, BN_, 384, 4, 11 + t, Kc, Vc);
        dec_attn_kernel<<<BN_, 128>>>(Qbuf, Kc, Vc, Kpe, Vpe,
                                      aresT + (size_t)(t - 1) * BN_ * 128, t);
    }

    // ---- batched output projection for pred[1..11] ----
    gemm1(aresT, outw_r, attn_out_b, pred + (size_t)BN_ * 128, 11 * BN_, 128, 1, 0, nullptr, nullptr);

    // ---- forecast ----
    gemm1(pred, forew_r, forecast_b, fore, LBN_, 256, 2, 0, nullptr, nullptr);
}

// round 4
// speedup vs baseline: 1.9354x; 1.0743x over previous
#include <cuda_runtime.h>
#include <cuda_fp16.h>
#include <math.h>
#include <stdint.h>

// ---------------- problem constants ----------------
#define B_    32
#define L_    12
#define N_    512
#define D_    128
#define BN_   16384      // B_*N_
#define LBN_  196608     // L_*BN_
#define FK_   256
#define T_    12
#define RES_ELEMS  25165824ULL   // 32*12*512*128
#define FORE_ELEMS 50331648ULL

// ---------------- device scratch (static, no allocations) ----------------
__device__ float  g_GI    [(size_t)LBN_ * 384];
__device__ float  g_GH    [(size_t)BN_  * 384];
__device__ float  g_rnn   [(size_t)LBN_ * 128];
__device__ float  g_rnnpe [(size_t)LBN_ * 128];
__device__ float  g_QKV   [(size_t)LBN_ * 384];
__device__ float  g_attn  [(size_t)LBN_ * 128];
__device__ float  g_Z0    [(size_t)LBN_ * 128];
__device__ __half g_Kc    [(size_t)23 * BN_ * 128];
__device__ __half g_Vc    [(size_t)23 * BN_ * 128];
__device__ float  g_pred  [(size_t)T_ * BN_ * 128];
__device__ float  g_aresT [(size_t)11 * BN_ * 128];
__device__ float  g_Qbuf  [(size_t)BN_ * 128];
__device__ float  g_GIdec [(size_t)BN_ * 384];
__device__ float  g_GHdec [(size_t)BN_ * 384];
__device__ float  g_g     [(size_t)BN_ * 128];
__device__ float  g_hlast [(size_t)BN_ * 128];
__device__ float  g_pe    [64 * 128];
__device__ float  g_Kpe   [24 * 128];
__device__ float  g_Vpe   [24 * 128];
// pre-rounded (tf32) weights
__device__ float g_wih_r  [49152];
__device__ float g_whh_r  [49152];
__device__ float g_inw_r  [49152];
__device__ float g_outw_r [16384];
__device__ float g_backw_r[16384];
__device__ float g_forew_r[32768];
__device__ float g_Wf     [49152];
__device__ float g_bf     [384];

// ---------------- tf32 helpers ----------------
__device__ __forceinline__ float rnd_tf32(float x) {
    unsigned u;
    asm("cvt.rna.tf32.f32 %0, %1;" : "=r"(u) : "f"(x));
    return __uint_as_float(u);
}

__device__ __forceinline__ void mma1688(float c[4], const unsigned a[4], const unsigned b[2]) {
    asm volatile(
        "mma.sync.aligned.m16n8k8.row.col.f32.tf32.tf32.f32 "
        "{%0,%1,%2,%3}, {%4,%5,%6,%7}, {%8,%9}, {%0,%1,%2,%3};\n"
        : "+f"(c[0]), "+f"(c[1]), "+f"(c[2]), "+f"(c[3])
        : "r"(a[0]), "r"(a[1]), "r"(a[2]), "r"(a[3]), "r"(b[0]), "r"(b[1]));
}

__device__ __forceinline__ float sigmoid_f(float x) {
    return __fdividef(1.f, 1.f + __expf(-x));
}
__device__ __forceinline__ float tanh_f(float x) {
    float ex = __expf(2.f * x);
    return 1.f - __fdividef(2.f, ex + 1.f);
}

// ---------------- templated tf32 GEMM: cp.async 3-stage ----------------
// C[M,N] = A[M,128] @ W[N,128]^T + bias ; W pre-rounded tf32; A rounded (or raw via APERM).
// MODE 0: plain. 1: plain + tf32-rounded out. 2: forecast permute (N=256).
// 3: QKV full write + scatter cols[128,384) -> fp16 Kc/Vc at row index (N=384).
// 4: proj: cols[0,128)->C stride128, cols[128,384) -> fp16 Kc/Vc at pos (N=384).
// 5: like 1 (N=128) + rows>=11*BN also copied to extra (pred[0]).
// 6: backcast+LN fused (N=128): u = X - relu(v+bias); rowwise LN; write to C in X-layout.
// APERM 1: A row remap (l*BN+b*512+n) -> X row (b*12+l)*512+n  (X read raw fp32).
// blockIdx.z selects pointer set (fused pair launches).
#define GSMEM_WORDS (2 * 3 * 2560)
#define GSMEM_BYTES (GSMEM_WORDS * 4)

template <int MODE, int APERM>
__global__ __launch_bounds__(256, 2) void gemm3(
    const float* __restrict__ A0, const float* __restrict__ W0,
    const float* __restrict__ bias0, float* __restrict__ C0,
    const float* __restrict__ A1, const float* __restrict__ W1,
    const float* __restrict__ bias1, float* __restrict__ C1,
    int M, int N, int pos,
    __half* __restrict__ Kc, __half* __restrict__ Vc,
    float* __restrict__ extra,
    const float* __restrict__ Xg, const float* __restrict__ gammap,
    const float* __restrict__ betap)
{
    extern __shared__ float sm[];
    const float* A    = blockIdx.z ? A1    : A0;
    const float* W    = blockIdx.z ? W1    : W0;
    const float* bias = blockIdx.z ? bias1 : bias0;
    float*       C    = blockIdx.z ? C1    : C0;

    const int tid = threadIdx.x, lane = tid & 31, warp = tid >> 5;
    const int wm = (warp >> 2) * 64;
    const int wn = (warp & 3) * 32;
    const int blockM = blockIdx.y * 128;
    const int blockN = blockIdx.x * 128;

    const int arow = tid >> 1;
    const int koff = (tid & 1) * 8;
    const float* Ag;
    if (APERM) {
        int grow = blockM + arow;
        int l = grow >> 14, rem = grow & 16383, b = rem >> 9, n = rem & 511;
        Ag = A + (((size_t)(b * 12 + l) * 512 + n) << 7) + koff;
    } else {
        Ag = A + (size_t)(blockM + arow) * 128 + koff;
    }
    const float* Wg = W + (size_t)(blockN + arow) * 128 + koff;
    uint32_t smb = (uint32_t)__cvta_generic_to_shared(sm);
    uint32_t a_s0 = smb + (uint32_t)(arow * 20 + koff) * 4;
    uint32_t w_s0 = smb + (uint32_t)(7680 + arow * 20 + koff) * 4;

    #define CP16(dst, src) asm volatile("cp.async.cg.shared.global [%0], [%1], 16;" :: "r"(dst), "l"(src))
    #define LOADSTAGE(S, KB) do { \
        uint32_t as_ = a_s0 + (S) * 2560u * 4u; const float* ag_ = Ag + (KB); \
        CP16(as_, ag_); CP16(as_ + 16, ag_ + 4); \
        uint32_t ws_ = w_s0 + (S) * 2560u * 4u; const float* wg_ = Wg + (KB); \
        CP16(ws_, wg_); CP16(ws_ + 16, wg_ + 4); \
    } while (0)

    float c[4][4][4];
    #pragma unroll
    for (int i = 0; i < 4; i++)
        #pragma unroll
        for (int j = 0; j < 4; j++)
            #pragma unroll
            for (int r = 0; r < 4; r++) c[i][j][r] = 0.f;

    LOADSTAGE(0, 0);
    asm volatile("cp.async.commit_group;");
    LOADSTAGE(1, 16);
    asm volatile("cp.async.commit_group;");

    #pragma unroll
    for (int it = 0; it < 8; ++it) {
        asm volatile("cp.async.wait_group 1;");
        __syncthreads();
        if (it + 2 < 8) LOADSTAGE((it + 2) % 3, (it + 2) * 16);
        asm volatile("cp.async.commit_group;");

        const float* Ab = sm + (it % 3) * 2560;
        const float* Wb = sm + 7680 + (it % 3) * 2560;
        #pragma unroll
        for (int ks = 0; ks < 16; ks += 8) {
            unsigned af[4][4], bf_[4][2];
            const int kc = ks + (lane & 3);
            #pragma unroll
            for (int mt = 0; mt < 4; mt++) {
                int row = wm + mt * 16 + (lane >> 2);
                af[mt][0] = __float_as_uint(Ab[row * 20 + kc]);
                af[mt][1] = __float_as_uint(Ab[(row + 8) * 20 + kc]);
                af[mt][2] = __float_as_uint(Ab[row * 20 + kc + 4]);
                af[mt][3] = __float_as_uint(Ab[(row + 8) * 20 + kc + 4]);
            }
            #pragma unroll
            for (int nt = 0; nt < 4; nt++) {
                int col = wn + nt * 8 + (lane >> 2);
                bf_[nt][0] = __float_as_uint(Wb[col * 20 + kc]);
                bf_[nt][1] = __float_as_uint(Wb[col * 20 + kc + 4]);
            }
            #pragma unroll
            for (int mt = 0; mt < 4; mt++)
                #pragma unroll
                for (int nt = 0; nt < 4; nt++)
                    mma1688(c[mt][nt], af[mt], bf_[nt]);
        }
    }
    #undef LOADSTAGE
    #undef CP16

    // ================= epilogues =================
    if (MODE == 6) {
        // fused backcast + residual LayerNorm. N == 128, blockN == 0.
        asm volatile("cp.async.wait_group 0;");
        __syncthreads();
        float* ssum = sm;          // [4][128]
        float* ssq  = sm + 512;    // [4][128]
        float ps[8], pq[8];
        #pragma unroll
        for (int p = 0; p < 8; p++) { ps[p] = 0.f; pq[p] = 0.f; }
        size_t xr[8];
        #pragma unroll
        for (int mt = 0; mt < 4; mt++) {
            int gr0 = blockM + wm + mt * 16 + (lane >> 2);
            int gr1 = gr0 + 8;
            int l0 = gr0 >> 14, r0 = gr0 & 16383;
            xr[mt * 2]     = (((size_t)((r0 >> 9) * 12 + l0) * 512 + (r0 & 511)) << 7);
            int l1 = gr1 >> 14, r1 = gr1 & 16383;
            xr[mt * 2 + 1] = (((size_t)((r1 >> 9) * 12 + l1) * 512 + (r1 & 511)) << 7);
            #pragma unroll
            for (int nt = 0; nt < 4; nt++) {
                int gc = wn + nt * 8 + 2 * (lane & 3);
                float bv0 = bias[gc], bv1 = bias[gc + 1];
                float u00 = Xg[xr[mt*2]   + gc]     - fmaxf(c[mt][nt][0] + bv0, 0.f);
                float u01 = Xg[xr[mt*2]   + gc + 1] - fmaxf(c[mt][nt][1] + bv1, 0.f);
                float u10 = Xg[xr[mt*2+1] + gc]     - fmaxf(c[mt][nt][2] + bv0, 0.f);
                float u11 = Xg[xr[mt*2+1] + gc + 1] - fmaxf(c[mt][nt][3] + bv1, 0.f);
                c[mt][nt][0] = u00; c[mt][nt][1] = u01;
                c[mt][nt][2] = u10; c[mt][nt][3] = u11;
                ps[mt*2]   += u00 + u01;  pq[mt*2]   += u00*u00 + u01*u01;
                ps[mt*2+1] += u10 + u11;  pq[mt*2+1] += u10*u10 + u11*u11;
            }
        }
        #pragma unroll
        for (int o = 1; o < 4; o <<= 1) {
            #pragma unroll
            for (int p = 0; p < 8; p++) {
                ps[p] += __shfl_xor_sync(0xffffffffu, ps[p], o);
                pq[p] += __shfl_xor_sync(0xffffffffu, pq[p], o);
            }
        }
        int wnIdx = warp & 3;
        if ((lane & 3) == 0) {
            #pragma unroll
            for (int mt = 0; mt < 4; mt++) {
                int lr = wm + mt * 16 + (lane >> 2);
                ssum[wnIdx * 128 + lr]     = ps[mt*2];
                ssq [wnIdx * 128 + lr]     = pq[mt*2];
                ssum[wnIdx * 128 + lr + 8] = ps[mt*2+1];
                ssq [wnIdx * 128 + lr + 8] = pq[mt*2+1];
            }
        }
        __syncthreads();
        #pragma unroll
        for (int mt = 0; mt < 4; mt++) {
            int lr0 = wm + mt * 16 + (lane >> 2);
            int lr1 = lr0 + 8;
            float s0 = ssum[lr0] + ssum[128+lr0] + ssum[256+lr0] + ssum[384+lr0];
            float q0 = ssq[lr0]  + ssq[128+lr0]  + ssq[256+lr0]  + ssq[384+lr0];
            float s1 = ssum[lr1] + ssum[128+lr1] + ssum[256+lr1] + ssum[384+lr1];
            float q1 = ssq[lr1]  + ssq[128+lr1]  + ssq[256+lr1]  + ssq[384+lr1];
            float mu0 = s0 * (1.f/128.f);
            float iv0 = rsqrtf(q0 * (1.f/128.f) - mu0*mu0 + 1e-5f);
            float mu1 = s1 * (1.f/128.f);
            float iv1 = rsqrtf(q1 * (1.f/128.f) - mu1*mu1 + 1e-5f);
            #pragma unroll
            for (int nt = 0; nt < 4; nt++) {
                int gc = wn + nt * 8 + 2 * (lane & 3);
                float g0 = gammap[gc], g1 = gammap[gc+1];
                float b0 = betap[gc],  b1 = betap[gc+1];
                C[xr[mt*2]   + gc]     = (c[mt][nt][0] - mu0) * iv0 * g0 + b0;
                C[xr[mt*2]   + gc + 1] = (c[mt][nt][1] - mu0) * iv0 * g1 + b1;
                C[xr[mt*2+1] + gc]     = (c[mt][nt][2] - mu1) * iv1 * g0 + b0;
                C[xr[mt*2+1] + gc + 1] = (c[mt][nt][3] - mu1) * iv1 * g1 + b1;
            }
        }
        return;
    }

    #pragma unroll
    for (int mt = 0; mt < 4; mt++) {
        #pragma unroll
        for (int nt = 0; nt < 4; nt++) {
            int gr = blockM + wm + mt * 16 + (lane >> 2);
            int gc = blockN + wn + nt * 8 + 2 * (lane & 3);
            float bv0 = bias[gc], bv1 = bias[gc + 1];
            float v00 = c[mt][nt][0] + bv0, v01 = c[mt][nt][1] + bv1;
            float v10 = c[mt][nt][2] + bv0, v11 = c[mt][nt][3] + bv1;
            int gr1 = gr + 8;
            if (MODE == 0) {
                float* p0 = C + (size_t)gr * N + gc;
                float* p1 = C + (size_t)gr1 * N + gc;
                p0[0] = v00; p0[1] = v01; p1[0] = v10; p1[1] = v11;
            } else if (MODE == 1 || MODE == 5) {
                float r00 = rnd_tf32(v00), r01 = rnd_tf32(v01);
                float r10 = rnd_tf32(v10), r11 = rnd_tf32(v11);
                float* p0 = C + (size_t)gr * N + gc;
                float* p1 = C + (size_t)gr1 * N + gc;
                p0[0] = r00; p0[1] = r01; p1[0] = r10; p1[1] = r11;
                if (MODE == 5) {
                    if (gr >= 11 * BN_) {
                        float* e0 = extra + (size_t)(gr - 11 * BN_) * 128 + gc;
                        e0[0] = r00; e0[1] = r01;
                    }
                    if (gr1 >= 11 * BN_) {
                        float* e1 = extra + (size_t)(gr1 - 11 * BN_) * 128 + gc;
                        e1[0] = r10; e1[1] = r11;
                    }
                }
            } else if (MODE == 2) {
                int t0 = gr >> 14, rem0 = gr & 16383;
                size_t or0 = (size_t)((rem0 >> 9) * 12 + t0) * 512 + (rem0 & 511);
                int t1 = gr1 >> 14, rem1 = gr1 & 16383;
                size_t or1 = (size_t)((rem1 >> 9) * 12 + t1) * 512 + (rem1 & 511);
                float* p0 = C + or0 * 256 + gc;
                float* p1 = C + or1 * 256 + gc;
                p0[0] = v00; p0[1] = v01; p1[0] = v10; p1[1] = v11;
            } else if (MODE == 3) {
                float* p0 = C + (size_t)gr * N + gc;
                float* p1 = C + (size_t)gr1 * N + gc;
                p0[0] = v00; p0[1] = v01; p1[0] = v10; p1[1] = v11;
                if (gc >= 128 && gc < 256) {
                    *(__half2*)(Kc + (size_t)gr * 128 + gc - 128)  = __floats2half2_rn(v00, v01);
                    *(__half2*)(Kc + (size_t)gr1 * 128 + gc - 128) = __floats2half2_rn(v10, v11);
                } else if (gc >= 256) {
                    *(__half2*)(Vc + (size_t)gr * 128 + gc - 256)  = __floats2half2_rn(v00, v01);
                    *(__half2*)(Vc + (size_t)gr1 * 128 + gc - 256) = __floats2half2_rn(v10, v11);
                }
            } else { // MODE 4
                if (gc < 128) {
                    float* p0 = C + (size_t)gr * 128 + gc;
                    float* p1 = C + (size_t)gr1 * 128 + gc;
                    p0[0] = v00; p0[1] = v01; p1[0] = v10; p1[1] = v11;
                } else if (gc < 256) {
                    *(__half2*)(Kc + ((size_t)pos * BN_ + gr) * 128 + gc - 128)  = __floats2half2_rn(v00, v01);
                    *(__half2*)(Kc + ((size_t)pos * BN_ + gr1) * 128 + gc - 128) = __floats2half2_rn(v10, v11);
                } else {
                    *(__half2*)(Vc + ((size_t)pos * BN_ + gr) * 128 + gc - 256)  = __floats2half2_rn(v00, v01);
                    *(__half2*)(Vc + ((size_t)pos * BN_ + gr1) * 128 + gc - 256) = __floats2half2_rn(v10, v11);
                }
            }
        }
    }
}

// ---------------- weight prep ----------------
__global__ void roundw_a_kernel(const float* __restrict__ w_ih, const float* __restrict__ w_hh,
                                const float* __restrict__ in_w,
                                float* wih_r, float* whh_r, float* inw_r) {
    int i = blockIdx.x * blockDim.x + threadIdx.x;
    if (i < 49152)       wih_r[i]         = rnd_tf32(w_ih[i]);
    else if (i < 98304)  whh_r[i - 49152] = rnd_tf32(w_hh[i - 49152]);
    else if (i < 147456) inw_r[i - 98304] = rnd_tf32(in_w[i - 98304]);
}
__global__ void roundw_b_kernel(const float* __restrict__ out_w, const float* __restrict__ back_w,
                                const float* __restrict__ fore_w,
                                float* outw_r, float* backw_r, float* forew_r) {
    int i = blockIdx.x * blockDim.x + threadIdx.x;
    if (i < 16384)      outw_r[i]          = rnd_tf32(out_w[i]);
    else if (i < 32768) backw_r[i - 16384] = rnd_tf32(back_w[i - 16384]);
    else if (i < 65536) forew_r[i - 32768] = rnd_tf32(fore_w[i - 32768]);
}

__global__ void pe_init_kernel(float* pe) {
    int idx = blockIdx.x * blockDim.x + threadIdx.x;
    if (idx >= 64 * 128) return;
    int pos = idx >> 7, d = idx & 127;
    int j = d >> 1;
    float div = expf((float)(2 * j) * (-logf(10000.f) / 128.f));
    float ang = (float)pos * div;
    pe[idx] = (d & 1) ? cosf(ang) : sinf(ang);
}

// Wf = w_ih @ attn_out_w (384x128), bf = w_ih @ b_out + b_ih
__global__ void wf_build_kernel(const float* __restrict__ w_ih, const float* __restrict__ out_w,
                                const float* __restrict__ b_out, const float* __restrict__ b_ih,
                                float* __restrict__ Wf, float* __restrict__ bf) {
    int idx = blockIdx.x * blockDim.x + threadIdx.x;
    if (idx >= 384 * 128) return;
    int r = idx >> 7, k = idx & 127;
    float acc = 0.f;
    #pragma unroll 4
    for (int j = 0; j < 128; j++) acc += w_ih[r * 128 + j] * out_w[j * 128 + k];
    Wf[idx] = rnd_tf32(acc);
    if (k == 0) {
        float b = 0.f;
        for (int j = 0; j < 128; j++) b += w_ih[r * 128 + j] * b_out[j];
        bf[r] = b + b_ih[r];
    }
}

__global__ void kvpe_kernel(const float* __restrict__ attn_in_w, const float* __restrict__ pe,
                            float* __restrict__ Kpe, float* __restrict__ Vpe) {
    int idx = blockIdx.x * blockDim.x + threadIdx.x;
    if (idx >= 24 * 256) return;
    int pos = idx >> 8, c = idx & 255;
    const float* wrow = attn_in_w + (size_t)(128 + c) * 128;
    const float* prow = pe + pos * 128;
    float acc = 0.f;
    #pragma unroll 4
    for (int d = 0; d < 128; d++) acc += wrow[d] * prow[d];
    if (c < 128) Kpe[pos * 128 + c] = acc;
    else         Vpe[pos * 128 + (c - 128)] = acc;
}

// ---------------- GRU gates (fused h / h+pe outputs) ----------------
// gh == nullptr -> use bhh broadcast (first step). h == nullptr -> h = 0.
__global__ void gru_gates_kernel(const float* __restrict__ gi, const float* __restrict__ gh,
                                 const float* __restrict__ h, float* __restrict__ hnew,
                                 float* __restrict__ hnext, const float* __restrict__ pe_row,
                                 const float* __restrict__ bhh, int total) {
    int idx = blockIdx.x * blockDim.x + threadIdx.x;
    if (idx >= total) return;
    int row = idx >> 7, d = idx & 127;
    size_t b3 = (size_t)row * 384;
    float ir = gi[b3 + d], iz = gi[b3 + 128 + d], in_ = gi[b3 + 256 + d];
    float hr, hz, hn;
    if (gh) { hr = gh[b3 + d]; hz = gh[b3 + 128 + d]; hn = gh[b3 + 256 + d]; }
    else    { hr = bhh[d];     hz = bhh[128 + d];     hn = bhh[256 + d]; }
    float hv = h ? h[idx] : 0.f;
    float r = sigmoid_f(ir + hr);
    float z = sigmoid_f(iz + hz);
    float n = tanh_f(in_ + r * hn);
    float out = (1.f - z) * n + z * hv;
    hnew[idx] = rnd_tf32(out);
    if (hnext) hnext[idx] = rnd_tf32(out + pe_row[d]);
}

// ---------------- encoder self-attention (warp per (bn,head)) ----------------
__global__ void enc_attn_kernel(const float* __restrict__ QKV, float* __restrict__ O) {
    int bn = blockIdx.x;
    int w = threadIdx.x >> 5, lane = threadIdx.x & 31;
    __shared__ float q[4][12][32];
    __shared__ float k[4][12][33];
    __shared__ float v[4][12][33];
    __shared__ float s[4][12][13];

    for (int e = lane; e < 12 * 32; e += 32) {
        int l = e >> 5, d = e & 31;
        size_t base = ((size_t)l * BN_ + bn) * 384 + w * 32 + d;
        q[w][l][d] = QKV[base];
        k[w][l][d] = QKV[base + 128];
        v[w][l][d] = QKV[base + 256];
    }
    __syncwarp();
    const float scale = 0.17677669529663687f;
    if (lane < 12) {
        int j = lane;
        #pragma unroll
        for (int i = 0; i < 12; i++) {
            float acc = 0.f;
            #pragma unroll
            for (int d = 0; d < 32; d++) acc += q[w][i][d] * k[w][j][d];
            s[w][i][j] = acc * scale;
        }
    }
    __syncwarp();
    if (lane < 12) {
        int i = lane;
        float mx = -1e30f;
        #pragma unroll
        for (int j = 0; j < 12; j++) mx = fmaxf(mx, s[w][i][j]);
        float sum = 0.f;
        #pragma unroll
        for (int j = 0; j < 12; j++) { float e = __expf(s[w][i][j] - mx); s[w][i][j] = e; sum += e; }
        float inv = __fdividef(1.f, sum);
        #pragma unroll
        for (int j = 0; j < 12; j++) s[w][i][j] *= inv;
    }
    __syncwarp();
    {
        int d = lane;
        #pragma unroll
        for (int i = 0; i < 12; i++) {
            float acc = 0.f;
            #pragma unroll
            for (int j = 0; j < 12; j++) acc += s[w][i][j] * v[w][j][d];
            O[((size_t)i * BN_ + bn) * 128 + w * 32 + d] = rnd_tf32(acc);
        }
    }
}

// ---------------- decode attention (fp16 KV, PE-drift multipliers) ----------------
__global__ void dec_attn_kernel(const float* __restrict__ Qbuf,
                                const __half* __restrict__ Kc, const __half* __restrict__ Vc,
                                const float* __restrict__ Kpe, const float* __restrict__ Vpe,
                                float* __restrict__ O, int t) {
    int len = 12 + t;
    int bn = blockIdx.x;
    int w = threadIdx.x >> 5, lane = threadIdx.x & 31;
    __shared__ float qs[4][32];
    __shared__ float Kb[4][23][33];
    __shared__ float Vb[4][23][33];
    __shared__ float aw[4][23];

    qs[w][lane] = Qbuf[(size_t)bn * 128 + w * 32 + lane];
    for (int e = lane; e < len * 32; e += 32) {
        int i = e >> 5, d = e & 31;
        size_t src = ((size_t)i * BN_ + bn) * 128 + w * 32 + d;
        Kb[w][i][d] = __half2float(Kc[src]);
        Vb[w][i][d] = __half2float(Vc[src]);
    }
    __syncwarp();

    float sc = -1e30f;
    int i = lane;
    if (i < len) {
        float m = (i < 12) ? (float)(t - 1) : (float)(t - i + 12);
        float a = 0.f, ap = 0.f;
        #pragma unroll
        for (int d = 0; d < 32; d++) {
            float qd = qs[w][d];
            a  += Kb[w][i][d] * qd;
            ap += Kpe[i * 128 + w * 32 + d] * qd;
        }
        sc = (a + m * ap) * 0.17677669529663687f;
    }
    float mx = sc;
    #pragma unroll
    for (int o = 16; o > 0; o >>= 1) mx = fmaxf(mx, __shfl_xor_sync(0xffffffffu, mx, o));
    float e = (i < len) ? __expf(sc - mx) : 0.f;
    float sum = e;
    #pragma unroll
    for (int o = 16; o > 0; o >>= 1) sum += __shfl_xor_sync(0xffffffffu, sum, o);
    float a = __fdividef(e, sum);
    if (i < len) aw[w][i] = a;
    __syncwarp();

    int d = lane;
    float acc = 0.f;
    for (int j = 0; j < len; j++) {
        float mj = (j < 12) ? (float)(t - 1) : (float)(t - j + 12);
        acc += aw[w][j] * (Vb[w][j][d] + mj * Vpe[j * 128 + w * 32 + d]);
    }
    O[(size_t)bn * 128 + w * 32 + d] = rnd_tf32(acc);
}

// ---------------- host orchestration ----------------
static inline float* symaddr(const void* sym) {
    void* p = nullptr;
    cudaGetSymbolAddress(&p, sym);
    return (float*)p;
}
static inline __half* symaddr_h(const void* sym) {
    void* p = nullptr;
    cudaGetSymbolAddress(&p, sym);
    return (__half*)p;
}

template <int MODE, int APERM>
static inline void launch_gemm(const float* A, const float* W, const float* b, float* C,
                               int M, int N, int pos = 0,
                               __half* Kc = nullptr, __half* Vc = nullptr,
                               float* extra = nullptr, const float* Xg = nullptr,
                               const float* gam = nullptr, const float* bet = nullptr) {
    gemm3<MODE, APERM><<<dim3(N / 128, M / 128, 1), 256, GSMEM_BYTES>>>(
        A, W, b, C, A, W, b, C, M, N, pos, Kc, Vc, extra, Xg, gam, bet);
}

extern "C" void kernel_launch(void* const* d_in, const int* in_sizes, int n_in,
                              void* d_out, int out_size) {
    const float* X          = (const float*)d_in[0];
    const float* gru_w_ih   = (const float*)d_in[1];
    const float* gru_w_hh   = (const float*)d_in[2];
    const float* gru_b_ih   = (const float*)d_in[3];
    const float* gru_b_hh   = (const float*)d_in[4];
    const float* attn_in_w  = (const float*)d_in[5];
    const float* attn_in_b  = (const float*)d_in[6];
    const float* attn_out_w = (const float*)d_in[7];
    const float* attn_out_b = (const float*)d_in[8];
    const float* backcast_w = (const float*)d_in[9];
    const float* backcast_b = (const float*)d_in[10];
    const float* forecast_w = (const float*)d_in[11];
    const float* forecast_b = (const float*)d_in[12];
    const float* ln_gamma   = (const float*)d_in[13];
    const float* ln_beta    = (const float*)d_in[14];

    float* out  = (float*)d_out;
    float* res  = out;
    float* fore = out + RES_ELEMS;

    float*  GI    = symaddr(g_GI);
    float*  GH    = symaddr(g_GH);
    float*  rnn   = symaddr(g_rnn);
    float*  rnnpe = symaddr(g_rnnpe);
    float*  QKV   = symaddr(g_QKV);
    float*  attn  = symaddr(g_attn);
    float*  Z0    = symaddr(g_Z0);
    __half* Kc    = symaddr_h(g_Kc);
    __half* Vc    = symaddr_h(g_Vc);
    float*  pred  = symaddr(g_pred);
    float*  aresT = symaddr(g_aresT);
    float*  Qbuf  = symaddr(g_Qbuf);
    float*  GIdec = symaddr(g_GIdec);
    float*  GHdec = symaddr(g_GHdec);
    float*  gbuf  = symaddr(g_g);
    float*  hlast = symaddr(g_hlast);
    float*  pe    = symaddr(g_pe);
    float*  Kpe   = symaddr(g_Kpe);
    float*  Vpe   = symaddr(g_Vpe);
    float*  wih_r   = symaddr(g_wih_r);
    float*  whh_r   = symaddr(g_whh_r);
    float*  inw_r   = symaddr(g_inw_r);
    float*  outw_r  = symaddr(g_outw_r);
    float*  backw_r = symaddr(g_backw_r);
    float*  forew_r = symaddr(g_forew_r);
    float*  Wf      = symaddr(g_Wf);
    float*  bf      = symaddr(g_bf);

    cudaFuncSetAttribute(gemm3<0,0>, cudaFuncAttributeMaxDynamicSharedMemorySize, GSMEM_BYTES);
    cudaFuncSetAttribute(gemm3<0,1>, cudaFuncAttributeMaxDynamicSharedMemorySize, GSMEM_BYTES);
    cudaFuncSetAttribute(gemm3<1,0>, cudaFuncAttributeMaxDynamicSharedMemorySize, GSMEM_BYTES);
    cudaFuncSetAttribute(gemm3<2,0>, cudaFuncAttributeMaxDynamicSharedMemorySize, GSMEM_BYTES);
    cudaFuncSetAttribute(gemm3<3,0>, cudaFuncAttributeMaxDynamicSharedMemorySize, GSMEM_BYTES);
    cudaFuncSetAttribute(gemm3<4,0>, cudaFuncAttributeMaxDynamicSharedMemorySize, GSMEM_BYTES);
    cudaFuncSetAttribute(gemm3<5,0>, cudaFuncAttributeMaxDynamicSharedMemorySize, GSMEM_BYTES);
    cudaFuncSetAttribute(gemm3<6,0>, cudaFuncAttributeMaxDynamicSharedMemorySize, GSMEM_BYTES);

    const int TPB = 256;

    // ---- prep (launch order chosen so launch #5 is the big GI GEMM) ----
    roundw_a_kernel<<<(147456 + TPB - 1) / TPB, TPB>>>(gru_w_ih, gru_w_hh, attn_in_w,
                                                       wih_r, whh_r, inw_r);
    roundw_b_kernel<<<(65536 + TPB - 1) / TPB, TPB>>>(attn_out_w, backcast_w, forecast_w,
                                                      outw_r, backw_r, forew_r);
    pe_init_kernel<<<(64 * 128 + TPB - 1) / TPB, TPB>>>(pe);
    wf_build_kernel<<<(49152 + TPB - 1) / TPB, TPB>>>(gru_w_ih, attn_out_w, attn_out_b,
                                                      gru_b_ih, Wf, bf);
    kvpe_kernel<<<(24 * 256 + TPB - 1) / TPB, TPB>>>(attn_in_w, pe, Kpe, Vpe);

    // ---- GI for all encoder steps (A read straight from X via row remap) ----
    launch_gemm<0, 1>(X, wih_r, gru_b_ih, GI, LBN_, 384);

    // ---- GRU encode: step 0 gates-only (gh = b_hh, h = 0), then 11x (gemm+gates).
    //      Each gates writes rnn[l] and rnnpe[l] = rnd(h + pe[l]). ----
    gru_gates_kernel<<<BN_ * 128 / TPB, TPB>>>(GI, nullptr, nullptr,
                                               rnn, rnnpe, pe, gru_b_hh, BN_ * 128);
    for (int l = 1; l < 12; l++) {
        launch_gemm<0, 0>(rnn + (size_t)(l - 1) * BN_ * 128, whh_r, gru_b_hh, GH, BN_, 384);
        gru_gates_kernel<<<BN_ * 128 / TPB, TPB>>>(GI + (size_t)l * BN_ * 384, GH,
                                                   rnn + (size_t)(l - 1) * BN_ * 128,
                                                   rnn + (size_t)l * BN_ * 128,
                                                   rnnpe + (size_t)l * BN_ * 128,
                                                   pe + l * 128, nullptr, BN_ * 128);
    }

    // ---- encoder MHA (QKV gemm scatters fp16 K/V into caches) ----
    launch_gemm<3, 0>(rnnpe, inw_r, attn_in_b, QKV, LBN_, 384, 0, Kc, Vc);
    enc_attn_kernel<<<BN_, 128>>>(QKV, attn);
    launch_gemm<5, 0>(attn, outw_r, attn_out_b, Z0, LBN_, 128, 0, nullptr, nullptr, pred);

    // ---- backcast + residual LN fused into one GEMM ----
    launch_gemm<6, 0>(Z0, backw_r, backcast_b, res, LBN_, 128, 0, nullptr, nullptr,
                      nullptr, X, ln_gamma, ln_beta);

    // ---- decode loop ----
    const float* hl = rnn + (size_t)11 * BN_ * 128;
    for (int t = 1; t <= 11; t++) {
        const float* prevA = (t == 1) ? attn + (size_t)11 * BN_ * 128
                                      : aresT + (size_t)(t - 2) * BN_ * 128;
        gemm3<0, 0><<<dim3(3, BN_ / 128, 2), 256, GSMEM_BYTES>>>(
            prevA, Wf, bf, GIdec, hl, whh_r, gru_b_hh, GHdec,
            BN_, 384, 0, nullptr, nullptr, nullptr, nullptr, nullptr, nullptr);
        gru_gates_kernel<<<BN_ * 128 / TPB, TPB>>>(GIdec, GHdec, hl, gbuf,
                                                   hlast, pe + (11 + t) * 128,
                                                   nullptr, BN_ * 128);
        hl = hlast;
        launch_gemm<4, 0>(gbuf, inw_r, attn_in_b, Qbuf, BN_, 384, 11 + t, Kc, Vc);
        dec_attn_kernel<<<BN_, 128>>>(Qbuf, Kc, Vc, Kpe, Vpe,
                                      aresT + (size_t)(t - 1) * BN_ * 128, t);
    }

    // ---- batched output projection for pred[1..11] ----
    launch_gemm<1, 0>(aresT, outw_r, attn_out_b, pred + (size_t)BN_ * 128, 11 * BN_, 128);

    // ---- forecast ----
    launch_gemm<2, 0>(pred, forew_r, forecast_b, fore, LBN_, 256);
}